// round 13
// baseline (speedup 1.0000x reference)
#include <cuda_runtime.h>
#include <cuda_bf16.h>
#include <math.h>
#include <cstdint>

#define I_ 16
#define T_ 64
#define Q_ 196
#define K_ 32
#define E_ 512
#define H_ 8
#define D_ 64
#define NT_ 512
#define NCTA_ 148
#define NU_ (I_*H_*T_)

#define OUT_N   (I_*T_*E_)
#define ATT_N   (I_*T_*H_*Q_*K_)
#define SC2_    ((float)(0.044194173824159216*1.4426950408889634))

#define SA_  200
#define MR_  208
#define EST_ 36
#define BBUF (K_*SA_*2)                 // 12800
#define VBUF (K_*D_*4)                  // 8192

#define YO_OFF   83200                  // A region [0,83200)
#define B_OFF    91392
#define V_OFF    116992
#define SE_OFF   133376                 // 208*36*4 = 29952
#define RINV_OFF 163328                 // 832
#define PE_OFF   164160                 // 2048
#define PA_OFF   166208                 // 2048
#define SMEM_ATTN 168256

typedef unsigned long long ull;

__device__ float g_query[I_*H_*Q_*D_];
__device__ float g_key  [T_*H_*K_*D_];
__device__ float g_value[T_*H_*K_*D_];
__device__ float g_pooled[I_*T_*E_];
__device__ float g_maskf[T_*K_];
__device__ unsigned char g_kb[(size_t)T_*H_*BBUF];

__device__ __forceinline__ unsigned smem_u32(const void* p) {
    unsigned a;
    asm("{ .reg .u64 t; cvta.to.shared.u64 t, %1; cvt.u32.u64 %0, t; }" : "=r"(a) : "l"(p));
    return a;
}
__device__ __forceinline__ ull fma2(ull a, ull b, ull c) {
    ull d; asm("fma.rn.f32x2 %0, %1, %2, %3;" : "=l"(d) : "l"(a), "l"(b), "l"(c)); return d;
}
__device__ __forceinline__ ull mul2(ull a, ull b) {
    ull d; asm("mul.rn.f32x2 %0, %1, %2;" : "=l"(d) : "l"(a), "l"(b)); return d;
}
__device__ __forceinline__ ull add2(ull a, ull b) {
    ull d; asm("add.rn.f32x2 %0, %1, %2;" : "=l"(d) : "l"(a), "l"(b)); return d;
}
__device__ __forceinline__ ull pack2(float x, float y) {
    ull d; asm("mov.b64 %0, {%1, %2};" : "=l"(d) : "f"(x), "f"(y)); return d;
}
__device__ __forceinline__ float lo2(ull a) { return __uint_as_float((unsigned)a); }
__device__ __forceinline__ float hi2(ull a) { return __uint_as_float((unsigned)(a >> 32)); }
__device__ __forceinline__ float ex2(float x) {
    float y; asm("ex2.approx.f32 %0, %1;" : "=f"(y) : "f"(x)); return y;
}
__device__ __forceinline__ float rcpa(float x) {
    float y; asm("rcp.approx.f32 %0, %1;" : "=f"(y) : "f"(x)); return y;
}
__device__ __forceinline__ ull lds1(unsigned a) {
    ull x; asm volatile("ld.shared.b64 %0, [%1];" : "=l"(x) : "r"(a)); return x;
}
__device__ __forceinline__ void lds2(unsigned a, ull& x, ull& y) {
    asm volatile("ld.shared.v2.b64 {%0,%1}, [%2];" : "=l"(x), "=l"(y) : "r"(a));
}
__device__ __forceinline__ void stg4(float* p, ull a, ull b) {
    asm volatile("{ .reg .f32 x,y,z,w; mov.b64 {x,y}, %1; mov.b64 {z,w}, %2;"
                 " st.global.v4.f32 [%0], {x,y,z,w}; }" :: "l"(p), "l"(a), "l"(b) : "memory");
}
__device__ __forceinline__ void cpa16(unsigned dst, const void* src) {
    asm volatile("cp.async.cg.shared.global [%0], [%1], 16;" :: "r"(dst), "l"(src) : "memory");
}
#define CPA_COMMIT() asm volatile("cp.async.commit_group;" ::: "memory")
#define CPA_WAIT()   asm volatile("cp.async.wait_group 0;" ::: "memory")
__device__ __forceinline__ void ldm_x4(unsigned a, unsigned& r0, unsigned& r1,
                                       unsigned& r2, unsigned& r3) {
    asm volatile("ldmatrix.sync.aligned.m8n8.x4.shared.b16 {%0,%1,%2,%3}, [%4];"
                 : "=r"(r0), "=r"(r1), "=r"(r2), "=r"(r3) : "r"(a));
}
__device__ __forceinline__ void ldm_x2(unsigned a, unsigned& r0, unsigned& r1) {
    asm volatile("ldmatrix.sync.aligned.m8n8.x2.shared.b16 {%0,%1}, [%2];"
                 : "=r"(r0), "=r"(r1) : "r"(a));
}
__device__ __forceinline__ void mma_bf16(float* c, unsigned a0, unsigned a1, unsigned a2,
                                         unsigned a3, unsigned b0, unsigned b1) {
    asm volatile("mma.sync.aligned.m16n8k16.row.col.f32.bf16.bf16.f32 "
                 "{%0,%1,%2,%3}, {%4,%5,%6,%7}, {%8,%9}, {%0,%1,%2,%3};"
                 : "+f"(c[0]), "+f"(c[1]), "+f"(c[2]), "+f"(c[3])
                 : "r"(a0), "r"(a1), "r"(a2), "r"(a3), "r"(b0), "r"(b1));
}

__global__ void mask_kernel(const void* mp) {
    __shared__ int mode;
    if (threadIdx.x == 0) {
        const unsigned char* b = (const unsigned char*)mp;
        int c3f = 0, cnz = 0;
        for (int k = 0; k < 512; k++) {
            if (b[4*k+3] == 0x3F) c3f++;
            if (b[4*k+1] | b[4*k+2]) cnz++;
        }
        mode = (c3f > 8) ? 2 : ((cnz > 8) ? 0 : 1);
    }
    __syncthreads();
    int m = mode;
    for (int idx = threadIdx.x; idx < T_*K_; idx += blockDim.x) {
        float v;
        if (m == 0)      v = ((const unsigned char*)mp)[idx] ? 1.f : 0.f;
        else if (m == 1) v = ((const int*)mp)[idx] ? 1.f : 0.f;
        else             v = (((const float*)mp)[idx] != 0.f) ? 1.f : 0.f;
        g_maskf[idx] = v;
    }
}

__global__ void proj_all(const float* __restrict__ image, const float* __restrict__ text,
                         const float* __restrict__ Wq, const float* __restrict__ Wk,
                         const float* __restrict__ Wv) {
    __shared__ float sA[64*33];
    __shared__ float sB[64*33];
    int bid = blockIdx.x;
    int which, h, rb;
    const float *X, *W;
    float* Y;
    if (bid < 392)      { which = 0; h = bid/49;       rb = bid%49;       X = image; W = Wq; Y = g_query; }
    else if (bid < 648) { which = 1; h = (bid-392)/32; rb = (bid-392)%32; X = text;  W = Wk; Y = g_key;   }
    else                { which = 2; h = (bid-648)/32; rb = (bid-648)%32; X = text;  W = Wv; Y = g_value; }
    int r0 = rb * 64;
    int tid = threadIdx.x;
    int tx = tid & 15, ty = tid >> 4;
    float acc[4][4] = {};
    #pragma unroll
    for (int kc = 0; kc < 64; kc += 32) {
        for (int idx = tid; idx < 2048; idx += 256) {
            int r = idx >> 5, kk = idx & 31;
            sA[r*33 + kk] = X[(r0 + r)*E_ + h*64 + kc + kk];
            sB[r*33 + kk] = W[r*64 + kc + kk];
        }
        __syncthreads();
        #pragma unroll
        for (int kk = 0; kk < 32; kk++) {
            float a[4], b[4];
            #pragma unroll
            for (int r = 0; r < 4; r++) a[r] = sA[(ty*4 + r)*33 + kk];
            #pragma unroll
            for (int c = 0; c < 4; c++) b[c] = sB[(tx*4 + c)*33 + kk];
            #pragma unroll
            for (int r = 0; r < 4; r++)
                #pragma unroll
                for (int c = 0; c < 4; c++) acc[r][c] += a[r] * b[c];
        }
        __syncthreads();
    }
    #pragma unroll
    for (int r = 0; r < 4; r++) {
        int row = r0 + ty*4 + r;
        long long obase;
        if (which == 0) { int i = row / Q_, q = row % Q_; obase = ((long long)(i*H_ + h)*Q_ + q)*64; }
        else            { int t = row >> 5, k = row & 31; obase = ((long long)(t*H_ + h)*K_ + k)*64; }
        #pragma unroll
        for (int c = 0; c < 4; c++)
            Y[obase + tx*4 + c] = acc[r][c];
    }
}

__global__ void kprep_kernel() {
    int th = blockIdx.x, tid = threadIdx.x;
    const float* Kg = g_key + (size_t)th*(K_*D_);
    unsigned char* B = g_kb + (size_t)th*BBUF;
    for (int idx = tid; idx < (K_*D_)/2; idx += 256) {
        int k = idx >> 5, d2 = (idx & 31)*2;
        float2 x = *(const float2*)&Kg[k*64 + d2];
        __nv_bfloat162 hi = __floats2bfloat162_rn(x.x, x.y);
        float2 hf = __bfloat1622float2(hi);
        __nv_bfloat162 lo = __floats2bfloat162_rn(x.x - hf.x, x.y - hf.y);
        *(__nv_bfloat162*)(B + (k*SA_ + d2)*2)       = hi;
        *(__nv_bfloat162*)(B + (k*SA_ + 64 + d2)*2)  = lo;
        *(__nv_bfloat162*)(B + (k*SA_ + 128 + d2)*2) = hi;
    }
}

__global__ void __launch_bounds__(NT_, 1)
attn_kernel(float* __restrict__ out, int wAttn, int wText) {
    extern __shared__ unsigned char smem[];
    unsigned sbase = smem_u32(smem);
    float* sYO   = (float*)(smem + YO_OFF);
    float* sV    = (float*)(smem + V_OFF);
    float* sE    = (float*)(smem + SE_OFF);
    float* sRinv = (float*)(smem + RINV_OFF);
    float* sPE   = (float*)(smem + PE_OFF);
    float* sPA   = (float*)(smem + PA_OFF);

    int tid = threadIdx.x, lane = tid & 31, wid = tid >> 5;
    int bid = blockIdx.x;
    int u0 = (bid * NU_) / NCTA_;
    int u1 = ((bid + 1) * NU_) / NCTA_;

    for (int idx = tid; idx < T_*K_; idx += NT_) {
        float m = g_maskf[idx];
        sYO[idx] = (m != 0.f) ? 0.f : -1e30f;
    }
    {
        int ihs = u0 >> 6, ts = u0 & 63, hs = ihs & 7;
        const float4* bs = (const float4*)(g_kb + (size_t)(ts*H_ + hs)*BBUF);
        float4* bd = (float4*)(smem + B_OFF);
        for (int idx = tid; idx < BBUF/16; idx += NT_) bd[idx] = bs[idx];
        const float4* vs = (const float4*)(g_value + (size_t)(ts*H_ + hs)*(K_*D_));
        float4* vd = (float4*)sV;
        for (int idx = tid; idx < (K_*D_)/4; idx += NT_) vd[idx] = vs[idx];
    }
    __syncthreads();

    unsigned af[12][4];
    int curih = -1;
    const ull S2 = pack2(SC2_, SC2_);
    int g = lane >> 2, q2 = lane & 3;

    for (int u = u0; u < u1; u++) {
        int ih = u >> 6, t = u & 63;
        int h = ih & 7, i = ih >> 3;
        int p = (u - u0) & 1;

        if (ih != curih) {
            unsigned* z = (unsigned*)smem;
            for (int idx = tid; idx < (MR_*SA_)/2; idx += NT_) z[idx] = 0u;
            __syncthreads();
            const float* Qg = g_query + (size_t)ih*(Q_*D_);
            unsigned char* A = smem;
            for (int idx = tid; idx < (Q_*D_)/2; idx += NT_) {
                int q = idx >> 5, d2 = (idx & 31)*2;
                float2 x = *(const float2*)&Qg[q*64 + d2];
                __nv_bfloat162 hi = __floats2bfloat162_rn(x.x, x.y);
                float2 hf = __bfloat1622float2(hi);
                __nv_bfloat162 lo = __floats2bfloat162_rn(x.x - hf.x, x.y - hf.y);
                *(__nv_bfloat162*)(A + (q*SA_ + d2)*2)       = hi;
                *(__nv_bfloat162*)(A + (q*SA_ + 64 + d2)*2)  = hi;
                *(__nv_bfloat162*)(A + (q*SA_ + 128 + d2)*2) = lo;
            }
            __syncthreads();
            if (wid < 13) {
                int lrow = lane & 15;
                int lcol = (lane < 16) ? 0 : 8;
                #pragma unroll
                for (int ks = 0; ks < 12; ks++) {
                    unsigned a = sbase + (unsigned)(((wid*16 + lrow)*SA_ + ks*16 + lcol)*2);
                    ldm_x4(a, af[ks][0], af[ks][1], af[ks][2], af[ks][3]);
                }
            }
            curih = ih;
        }

        long long tileOff = ((long long)(i*T_ + t)*H_ + h) * (Q_*K_);
        int r0 = wid*16 + g;
        unsigned yoT = sbase + YO_OFF + (unsigned)(t*128);

        // ---- phase 1: MMA + exp + rowsum + STS e + col partials; warps 13-15 cp.async ----
        if (wid < 13) {
            unsigned sBb = sbase + B_OFF + (unsigned)(p*BBUF);
            int ln = lane & 15;
            int bn = ln & 7;
            int bc = (ln < 8) ? 0 : 8;
            float c[4][4] = {};
            #pragma unroll
            for (int ks = 0; ks < 12; ks++) {
                unsigned b0[4], b1[4];
                #pragma unroll
                for (int nt = 0; nt < 4; nt++) {
                    unsigned a = sBb + (unsigned)(((nt*8 + bn)*SA_ + ks*16 + bc)*2);
                    ldm_x2(a, b0[nt], b1[nt]);
                }
                #pragma unroll
                for (int nt = 0; nt < 4; nt++)
                    mma_bf16(c[nt], af[ks][0], af[ks][1], af[ks][2], af[ks][3], b0[nt], b1[nt]);
            }
            ull e0[4], e1[4];
            ull rs0 = pack2(0.f, 0.f), rs1 = pack2(0.f, 0.f);
            #pragma unroll
            for (int nt = 0; nt < 4; nt++) {
                ull yo = lds1(yoT + (unsigned)((nt*8 + 2*q2)*4));
                ull v0 = fma2(pack2(c[nt][0], c[nt][1]), S2, yo);
                ull v1 = fma2(pack2(c[nt][2], c[nt][3]), S2, yo);
                e0[nt] = pack2(ex2(lo2(v0)), ex2(hi2(v0)));
                e1[nt] = pack2(ex2(lo2(v1)), ex2(hi2(v1)));
                rs0 = add2(rs0, e0[nt]);
                rs1 = add2(rs1, e1[nt]);
            }
            // e -> sE (fragment STS, read coalesced in phase 2)
            #pragma unroll
            for (int nt = 0; nt < 4; nt++) {
                int col = nt*8 + 2*q2;
                *(float2*)&sE[r0*EST_ + col]       = make_float2(lo2(e0[nt]), hi2(e0[nt]));
                *(float2*)&sE[(r0 + 8)*EST_ + col] = make_float2(lo2(e1[nt]), hi2(e1[nt]));
            }
            float rsum0 = lo2(rs0) + hi2(rs0);
            float rsum1 = lo2(rs1) + hi2(rs1);
            rsum0 += __shfl_xor_sync(0xffffffffu, rsum0, 1);
            rsum0 += __shfl_xor_sync(0xffffffffu, rsum0, 2);
            rsum1 += __shfl_xor_sync(0xffffffffu, rsum1, 1);
            rsum1 += __shfl_xor_sync(0xffffffffu, rsum1, 2);
            float rinv0 = rcpa(rsum0), rinv1 = rcpa(rsum1);
            if (q2 == 0) { sRinv[r0] = rinv0; sRinv[r0 + 8] = rinv1; }
            // in-register column partials (mask padding rows)
            float m0f = (r0 < Q_) ? 1.f : 0.f;
            float m1f = (r0 + 8 < Q_) ? 1.f : 0.f;
            ull M0 = pack2(m0f, m0f), M1 = pack2(m1f, m1f);
            ull rv0p = pack2(rinv0*m0f, rinv0*m0f);
            ull rv1p = pack2(rinv1*m1f, rinv1*m1f);
            #pragma unroll
            for (int nt = 0; nt < 4; nt++) {
                ull pe = fma2(e1[nt], M1, mul2(e0[nt], M0));
                ull pa = fma2(e1[nt], rv1p, mul2(e0[nt], rv0p));
                float pex = lo2(pe), pey = hi2(pe), pax = lo2(pa), pay = hi2(pa);
                #pragma unroll
                for (int o = 4; o <= 16; o <<= 1) {
                    pex += __shfl_xor_sync(0xffffffffu, pex, o);
                    pey += __shfl_xor_sync(0xffffffffu, pey, o);
                    pax += __shfl_xor_sync(0xffffffffu, pax, o);
                    pay += __shfl_xor_sync(0xffffffffu, pay, o);
                }
                if (lane < 4) {
                    int col = nt*8 + 2*lane;
                    sPE[wid*32 + col] = pex; sPE[wid*32 + col + 1] = pey;
                    sPA[wid*32 + col] = pax; sPA[wid*32 + col + 1] = pay;
                }
            }
        } else if (u + 1 < u1) {
            int un = u + 1, ihn = un >> 6, tn = un & 63, hn = ihn & 7;
            int pn = p ^ 1;
            int idx0 = tid - 416;
            const unsigned char* bs = g_kb + (size_t)(tn*H_ + hn)*BBUF;
            unsigned bd = sbase + B_OFF + (unsigned)(pn*BBUF);
            for (int idx = idx0; idx < BBUF/16; idx += 96)
                cpa16(bd + idx*16, bs + idx*16);
            const unsigned char* vs = (const unsigned char*)(g_value + (size_t)(tn*H_ + hn)*(K_*D_));
            unsigned vd = sbase + V_OFF + (unsigned)(pn*VBUF);
            for (int idx = idx0; idx < VBUF/16; idx += 96)
                cpa16(vd + idx*16, vs + idx*16);
            CPA_COMMIT();
        }
        __syncthreads();

        // ---- phase 2: per-warp colsum reduce + coalesced writeout + pooled ----
        float pe = 0.f, pa = 0.f;
        #pragma unroll
        for (int w = 0; w < 13; w++) {
            pe += sPE[w*32 + lane];
            pa += sPA[w*32 + lane];
        }
        float yv = sYO[t*K_ + lane];
        float ta = (yv == 0.f) ? rcpa(pe) : 0.f;
        float tb = (yv == 0.f) ? 0.f : (1.f / (float)Q_);

        if (wAttn | wText) {
            float* ap = out + OUT_N + tileOff;
            float* tp = out + OUT_N + (long long)ATT_N + tileOff;
            #pragma unroll
            for (int kk = 0; kk < 4; kk++) {
                int idx = tid + kk*NT_;
                if (idx >= Q_*8) break;             // warp-uniform (1568 = 49 warps)
                int q = idx >> 3, c = idx & 7;
                ull ev0, ev1;
                lds2(sbase + SE_OFF + (unsigned)((q*EST_ + 4*c)*4), ev0, ev1);
                if (wAttn) {
                    float rq = sRinv[q];
                    ull rv = pack2(rq, rq);
                    stg4(ap + q*K_ + 4*c, mul2(ev0, rv), mul2(ev1, rv));
                }
                if (wText) {
                    float tax = __shfl_sync(0xffffffffu, ta, 4*c);
                    float tay = __shfl_sync(0xffffffffu, ta, 4*c + 1);
                    float taz = __shfl_sync(0xffffffffu, ta, 4*c + 2);
                    float taw = __shfl_sync(0xffffffffu, ta, 4*c + 3);
                    float tbx = __shfl_sync(0xffffffffu, tb, 4*c);
                    float tby = __shfl_sync(0xffffffffu, tb, 4*c + 1);
                    float tbz = __shfl_sync(0xffffffffu, tb, 4*c + 2);
                    float tbw = __shfl_sync(0xffffffffu, tb, 4*c + 3);
                    stg4(tp + q*K_ + 4*c,
                         fma2(ev0, pack2(tax, tay), pack2(tbx, tby)),
                         fma2(ev1, pack2(taz, taw), pack2(tbz, tbw)));
                }
            }
        }
        if (wid == 13 || wid == 14) {
            int d = (wid - 13)*32 + lane;
            const float* vv = sV + p*(K_*D_);
            float a = 0.f;
            #pragma unroll
            for (int k = 0; k < 32; k++)
                a = fmaf(__shfl_sync(0xffffffffu, pa, k), vv[k*D_ + d], a);
            g_pooled[(long long)(i*T_ + t)*E_ + h*64 + d] = a * (1.f / (float)Q_);
        }
        CPA_WAIT();
        __syncthreads();
    }
}

__global__ void fc_kernel(const float* __restrict__ Wo, const float* __restrict__ bo,
                          float* __restrict__ out) {
    __shared__ float sA[64*33];
    __shared__ float sB[64*33];
    int rt = blockIdx.x * 64;
    int ct = blockIdx.y * 64;
    int tid = threadIdx.x;
    int tx = tid & 15, ty = tid >> 4;
    float acc[4][4] = {};
    float ra[8], rb[8];
    #pragma unroll
    for (int j = 0; j < 8; j++) {
        int idx = tid + j*256;
        int r = idx >> 5, kk = idx & 31;
        ra[j] = g_pooled[(rt + r)*E_ + kk];
        rb[j] = Wo[(ct + r)*E_ + kk];
    }
    for (int kc = 0; kc < E_; kc += 32) {
        #pragma unroll
        for (int j = 0; j < 8; j++) {
            int idx = tid + j*256;
            int r = idx >> 5, kk = idx & 31;
            sA[r*33 + kk] = ra[j];
            sB[r*33 + kk] = rb[j];
        }
        __syncthreads();
        if (kc + 32 < E_) {
            #pragma unroll
            for (int j = 0; j < 8; j++) {
                int idx = tid + j*256;
                int r = idx >> 5, kk = idx & 31;
                ra[j] = g_pooled[(rt + r)*E_ + kc + 32 + kk];
                rb[j] = Wo[(ct + r)*E_ + kc + 32 + kk];
            }
        }
        #pragma unroll
        for (int kk = 0; kk < 32; kk++) {
            float a[4], b[4];
            #pragma unroll
            for (int r = 0; r < 4; r++) a[r] = sA[(ty*4 + r)*33 + kk];
            #pragma unroll
            for (int c = 0; c < 4; c++) b[c] = sB[(tx*4 + c)*33 + kk];
            #pragma unroll
            for (int r = 0; r < 4; r++)
                #pragma unroll
                for (int c = 0; c < 4; c++) acc[r][c] += a[r] * b[c];
        }
        __syncthreads();
    }
    #pragma unroll
    for (int r = 0; r < 4; r++)
        #pragma unroll
        for (int c = 0; c < 4; c++)
            out[(rt + ty*4 + r)*E_ + ct + tx*4 + c] = acc[r][c] + bo[ct + tx*4 + c];
}

extern "C" void kernel_launch(void* const* d_in, const int* in_sizes, int n_in,
                              void* d_out, int out_size) {
    const float* image = (const float*)d_in[0];
    const float* text  = (const float*)d_in[1];
    const void*  mask  =                d_in[2];
    const float* Wq    = (const float*)d_in[3];
    const float* Wk    = (const float*)d_in[4];
    const float* Wv    = (const float*)d_in[5];
    const float* Wo    = (const float*)d_in[6];
    const float* bo    = (const float*)d_in[7];
    float* out = (float*)d_out;

    cudaFuncSetAttribute(attn_kernel, cudaFuncAttributeMaxDynamicSharedMemorySize, SMEM_ATTN);

    mask_kernel<<<1, 256>>>(mask);
    proj_all<<<904, 256>>>(image, text, Wq, Wk, Wv);
    kprep_kernel<<<T_*H_, 256>>>();

    int wAttn = out_size >= (OUT_N + ATT_N);
    int wText = out_size >= (OUT_N + 2*ATT_N);
    attn_kernel<<<NCTA_, NT_, SMEM_ATTN>>>(out, wAttn, wText);

    if (out_size >= OUT_N)
        fc_kernel<<<dim3(16, 8), 256>>>(Wo, bo, out);
}

// round 14
// speedup vs baseline: 1.0227x; 1.0227x over previous
#include <cuda_runtime.h>
#include <cuda_bf16.h>
#include <math.h>
#include <cstdint>

#define I_ 16
#define T_ 64
#define Q_ 196
#define K_ 32
#define E_ 512
#define H_ 8
#define D_ 64
#define NT_ 512
#define NCTA_ 148
#define NU_ (I_*H_*T_)

#define OUT_N   (I_*T_*E_)
#define ATT_N   (I_*T_*H_*Q_*K_)
#define SC2_    ((float)(0.044194173824159216*1.4426950408889634))

#define SA_  136                        // K=128 dedup layout [hi|lo], padded stride
#define MR_  208
#define EST_ 36
#define BBUF (K_*SA_*2)                 // 8704
#define VBUF (K_*D_*4)                  // 8192
#define ABYTES (MR_*SA_*2)              // 56576

#define SE_OFF   0                      // overlaps A region (boundary-only conflict)
#define YO_OFF   56576
#define B_OFF    64768
#define V_OFF    (B_OFF + 2*BBUF)       // 82176
#define RINV_OFF (V_OFF + 2*VBUF)       // 98560
#define PE_OFF   99392
#define PA_OFF   101440
#define SMEM_ATTN 103488

typedef unsigned long long ull;

__device__ float g_query[I_*H_*Q_*D_];
__device__ float g_key  [T_*H_*K_*D_];
__device__ float g_value[T_*H_*K_*D_];
__device__ float g_pooled[I_*T_*E_];
__device__ float g_maskf[T_*K_];
__device__ unsigned char g_kb[(size_t)T_*H_*BBUF];

__device__ __forceinline__ unsigned smem_u32(const void* p) {
    unsigned a;
    asm("{ .reg .u64 t; cvta.to.shared.u64 t, %1; cvt.u32.u64 %0, t; }" : "=r"(a) : "l"(p));
    return a;
}
__device__ __forceinline__ ull fma2(ull a, ull b, ull c) {
    ull d; asm("fma.rn.f32x2 %0, %1, %2, %3;" : "=l"(d) : "l"(a), "l"(b), "l"(c)); return d;
}
__device__ __forceinline__ ull mul2(ull a, ull b) {
    ull d; asm("mul.rn.f32x2 %0, %1, %2;" : "=l"(d) : "l"(a), "l"(b)); return d;
}
__device__ __forceinline__ ull add2(ull a, ull b) {
    ull d; asm("add.rn.f32x2 %0, %1, %2;" : "=l"(d) : "l"(a), "l"(b)); return d;
}
__device__ __forceinline__ ull pack2(float x, float y) {
    ull d; asm("mov.b64 %0, {%1, %2};" : "=l"(d) : "f"(x), "f"(y)); return d;
}
__device__ __forceinline__ float lo2(ull a) { return __uint_as_float((unsigned)a); }
__device__ __forceinline__ float hi2(ull a) { return __uint_as_float((unsigned)(a >> 32)); }
__device__ __forceinline__ float ex2(float x) {
    float y; asm("ex2.approx.f32 %0, %1;" : "=f"(y) : "f"(x)); return y;
}
__device__ __forceinline__ float rcpa(float x) {
    float y; asm("rcp.approx.f32 %0, %1;" : "=f"(y) : "f"(x)); return y;
}
__device__ __forceinline__ ull lds1(unsigned a) {
    ull x; asm volatile("ld.shared.b64 %0, [%1];" : "=l"(x) : "r"(a)); return x;
}
__device__ __forceinline__ void lds2(unsigned a, ull& x, ull& y) {
    asm volatile("ld.shared.v2.b64 {%0,%1}, [%2];" : "=l"(x), "=l"(y) : "r"(a));
}
__device__ __forceinline__ void stg4(float* p, ull a, ull b) {
    asm volatile("{ .reg .f32 x,y,z,w; mov.b64 {x,y}, %1; mov.b64 {z,w}, %2;"
                 " st.global.v4.f32 [%0], {x,y,z,w}; }" :: "l"(p), "l"(a), "l"(b) : "memory");
}
__device__ __forceinline__ void cpa16(unsigned dst, const void* src) {
    asm volatile("cp.async.cg.shared.global [%0], [%1], 16;" :: "r"(dst), "l"(src) : "memory");
}
#define CPA_COMMIT() asm volatile("cp.async.commit_group;" ::: "memory")
#define CPA_WAIT()   asm volatile("cp.async.wait_group 0;" ::: "memory")
__device__ __forceinline__ void ldm_x4(unsigned a, unsigned& r0, unsigned& r1,
                                       unsigned& r2, unsigned& r3) {
    asm volatile("ldmatrix.sync.aligned.m8n8.x4.shared.b16 {%0,%1,%2,%3}, [%4];"
                 : "=r"(r0), "=r"(r1), "=r"(r2), "=r"(r3) : "r"(a));
}
__device__ __forceinline__ void ldm_x2(unsigned a, unsigned& r0, unsigned& r1) {
    asm volatile("ldmatrix.sync.aligned.m8n8.x2.shared.b16 {%0,%1}, [%2];"
                 : "=r"(r0), "=r"(r1) : "r"(a));
}
__device__ __forceinline__ void mma_bf16(float* c, const unsigned* a, unsigned b0, unsigned b1) {
    asm volatile("mma.sync.aligned.m16n8k16.row.col.f32.bf16.bf16.f32 "
                 "{%0,%1,%2,%3}, {%4,%5,%6,%7}, {%8,%9}, {%0,%1,%2,%3};"
                 : "+f"(c[0]), "+f"(c[1]), "+f"(c[2]), "+f"(c[3])
                 : "r"(a[0]), "r"(a[1]), "r"(a[2]), "r"(a[3]), "r"(b0), "r"(b1));
}

__global__ void mask_kernel(const void* mp) {
    __shared__ int mode;
    if (threadIdx.x == 0) {
        const unsigned char* b = (const unsigned char*)mp;
        int c3f = 0, cnz = 0;
        for (int k = 0; k < 512; k++) {
            if (b[4*k+3] == 0x3F) c3f++;
            if (b[4*k+1] | b[4*k+2]) cnz++;
        }
        mode = (c3f > 8) ? 2 : ((cnz > 8) ? 0 : 1);
    }
    __syncthreads();
    int m = mode;
    for (int idx = threadIdx.x; idx < T_*K_; idx += blockDim.x) {
        float v;
        if (m == 0)      v = ((const unsigned char*)mp)[idx] ? 1.f : 0.f;
        else if (m == 1) v = ((const int*)mp)[idx] ? 1.f : 0.f;
        else             v = (((const float*)mp)[idx] != 0.f) ? 1.f : 0.f;
        g_maskf[idx] = v;
    }
}

__global__ void proj_all(const float* __restrict__ image, const float* __restrict__ text,
                         const float* __restrict__ Wq, const float* __restrict__ Wk,
                         const float* __restrict__ Wv) {
    __shared__ float sA[64*33];
    __shared__ float sB[64*33];
    int bid = blockIdx.x;
    int which, h, rb;
    const float *X, *W;
    float* Y;
    if (bid < 392)      { which = 0; h = bid/49;       rb = bid%49;       X = image; W = Wq; Y = g_query; }
    else if (bid < 648) { which = 1; h = (bid-392)/32; rb = (bid-392)%32; X = text;  W = Wk; Y = g_key;   }
    else                { which = 2; h = (bid-648)/32; rb = (bid-648)%32; X = text;  W = Wv; Y = g_value; }
    int r0 = rb * 64;
    int tid = threadIdx.x;
    int tx = tid & 15, ty = tid >> 4;
    float acc[4][4] = {};
    #pragma unroll
    for (int kc = 0; kc < 64; kc += 32) {
        for (int idx = tid; idx < 2048; idx += 256) {
            int r = idx >> 5, kk = idx & 31;
            sA[r*33 + kk] = X[(r0 + r)*E_ + h*64 + kc + kk];
            sB[r*33 + kk] = W[r*64 + kc + kk];
        }
        __syncthreads();
        #pragma unroll
        for (int kk = 0; kk < 32; kk++) {
            float a[4], b[4];
            #pragma unroll
            for (int r = 0; r < 4; r++) a[r] = sA[(ty*4 + r)*33 + kk];
            #pragma unroll
            for (int c = 0; c < 4; c++) b[c] = sB[(tx*4 + c)*33 + kk];
            #pragma unroll
            for (int r = 0; r < 4; r++)
                #pragma unroll
                for (int c = 0; c < 4; c++) acc[r][c] += a[r] * b[c];
        }
        __syncthreads();
    }
    #pragma unroll
    for (int r = 0; r < 4; r++) {
        int row = r0 + ty*4 + r;
        long long obase;
        if (which == 0) { int i = row / Q_, q = row % Q_; obase = ((long long)(i*H_ + h)*Q_ + q)*64; }
        else            { int t = row >> 5, k = row & 31; obase = ((long long)(t*H_ + h)*K_ + k)*64; }
        #pragma unroll
        for (int c = 0; c < 4; c++)
            Y[obase + tx*4 + c] = acc[r][c];
    }
}

// K -> bf16 [hi|lo] (K=128 dedup layout, stride SA_)
__global__ void kprep_kernel() {
    int th = blockIdx.x, tid = threadIdx.x;
    const float* Kg = g_key + (size_t)th*(K_*D_);
    unsigned char* B = g_kb + (size_t)th*BBUF;
    for (int idx = tid; idx < (K_*D_)/2; idx += 256) {
        int k = idx >> 5, d2 = (idx & 31)*2;
        float2 x = *(const float2*)&Kg[k*64 + d2];
        __nv_bfloat162 hi = __floats2bfloat162_rn(x.x, x.y);
        float2 hf = __bfloat1622float2(hi);
        __nv_bfloat162 lo = __floats2bfloat162_rn(x.x - hf.x, x.y - hf.y);
        *(__nv_bfloat162*)(B + (k*SA_ + d2)*2)      = hi;
        *(__nv_bfloat162*)(B + (k*SA_ + 64 + d2)*2) = lo;
    }
}

__global__ void __launch_bounds__(NT_, 1)
attn_kernel(float* __restrict__ out, int wAttn, int wText) {
    extern __shared__ unsigned char smem[];
    unsigned sbase = smem_u32(smem);
    float* sYO   = (float*)(smem + YO_OFF);
    float* sV    = (float*)(smem + V_OFF);
    float* sE    = (float*)(smem + SE_OFF);
    float* sRinv = (float*)(smem + RINV_OFF);
    float* sPE   = (float*)(smem + PE_OFF);
    float* sPA   = (float*)(smem + PA_OFF);

    int tid = threadIdx.x, lane = tid & 31, wid = tid >> 5;
    int bid = blockIdx.x;
    int u0 = (bid * NU_) / NCTA_;
    int u1 = ((bid + 1) * NU_) / NCTA_;

    for (int idx = tid; idx < T_*K_; idx += NT_) {
        float m = g_maskf[idx];
        sYO[idx] = (m != 0.f) ? 0.f : -1e30f;
    }
    {
        int ihs = u0 >> 6, ts = u0 & 63, hs = ihs & 7;
        const float4* bs = (const float4*)(g_kb + (size_t)(ts*H_ + hs)*BBUF);
        float4* bd = (float4*)(smem + B_OFF);
        for (int idx = tid; idx < BBUF/16; idx += NT_) bd[idx] = bs[idx];
        const float4* vs = (const float4*)(g_value + (size_t)(ts*H_ + hs)*(K_*D_));
        float4* vd = (float4*)sV;
        for (int idx = tid; idx < (K_*D_)/4; idx += NT_) vd[idx] = vs[idx];
    }
    __syncthreads();

    unsigned ahi[4][4], alo[4][4];
    int curih = -1;
    const ull S2 = pack2(SC2_, SC2_);
    int g = lane >> 2, q2 = lane & 3;

    for (int u = u0; u < u1; u++) {
        int ih = u >> 6, t = u & 63;
        int h = ih & 7, i = ih >> 3;
        int p = (u - u0) & 1;

        if (ih != curih) {
            unsigned* z = (unsigned*)smem;
            for (int idx = tid; idx < ABYTES/4; idx += NT_) z[idx] = 0u;
            __syncthreads();
            const float* Qg = g_query + (size_t)ih*(Q_*D_);
            unsigned char* A = smem;
            for (int idx = tid; idx < (Q_*D_)/2; idx += NT_) {
                int q = idx >> 5, d2 = (idx & 31)*2;
                float2 x = *(const float2*)&Qg[q*64 + d2];
                __nv_bfloat162 hi = __floats2bfloat162_rn(x.x, x.y);
                float2 hf = __bfloat1622float2(hi);
                __nv_bfloat162 lo = __floats2bfloat162_rn(x.x - hf.x, x.y - hf.y);
                *(__nv_bfloat162*)(A + (q*SA_ + d2)*2)      = hi;
                *(__nv_bfloat162*)(A + (q*SA_ + 64 + d2)*2) = lo;
            }
            __syncthreads();
            if (wid < 13) {
                int lrow = lane & 15;
                int lcol = (lane < 16) ? 0 : 8;
                #pragma unroll
                for (int ks = 0; ks < 4; ks++) {
                    unsigned a0 = sbase + (unsigned)(((wid*16 + lrow)*SA_ + ks*16 + lcol)*2);
                    ldm_x4(a0, ahi[ks][0], ahi[ks][1], ahi[ks][2], ahi[ks][3]);
                    unsigned a1 = sbase + (unsigned)(((wid*16 + lrow)*SA_ + 64 + ks*16 + lcol)*2);
                    ldm_x4(a1, alo[ks][0], alo[ks][1], alo[ks][2], alo[ks][3]);
                }
            }
            curih = ih;
            __syncthreads();   // A region becomes sE again next
        }

        long long tileOff = ((long long)(i*T_ + t)*H_ + h) * (Q_*K_);
        int r0 = wid*16 + g;
        unsigned yoT = sbase + YO_OFF + (unsigned)(t*128);

        // ---- phase 1: dedup MMA + exp + rowsum + STS e + col partials; 13-15 cp.async ----
        if (wid < 13) {
            unsigned sBb = sbase + B_OFF + (unsigned)(p*BBUF);
            int ln = lane & 15;
            int bn = ln & 7;
            int bc = (ln < 8) ? 0 : 8;
            float c[4][4] = {};
            #pragma unroll
            for (int ks = 0; ks < 4; ks++) {
                unsigned bh0[4], bh1[4], bl0[4], bl1[4];
                #pragma unroll
                for (int nt = 0; nt < 4; nt++) {
                    unsigned ab = sBb + (unsigned)(((nt*8 + bn)*SA_ + ks*16 + bc)*2);
                    ldm_x2(ab, bh0[nt], bh1[nt]);
                    ldm_x2(ab + 128, bl0[nt], bl1[nt]);   // +64 elems = +128 B
                }
                #pragma unroll
                for (int nt = 0; nt < 4; nt++) {
                    mma_bf16(c[nt], ahi[ks], bh0[nt], bh1[nt]);   // Qhi*Khi
                    mma_bf16(c[nt], alo[ks], bh0[nt], bh1[nt]);   // Qlo*Khi
                    mma_bf16(c[nt], ahi[ks], bl0[nt], bl1[nt]);   // Qhi*Klo
                }
            }
            ull e0[4], e1[4];
            ull rs0 = pack2(0.f, 0.f), rs1 = pack2(0.f, 0.f);
            #pragma unroll
            for (int nt = 0; nt < 4; nt++) {
                ull yo = lds1(yoT + (unsigned)((nt*8 + 2*q2)*4));
                ull v0 = fma2(pack2(c[nt][0], c[nt][1]), S2, yo);
                ull v1 = fma2(pack2(c[nt][2], c[nt][3]), S2, yo);
                e0[nt] = pack2(ex2(lo2(v0)), ex2(hi2(v0)));
                e1[nt] = pack2(ex2(lo2(v1)), ex2(hi2(v1)));
                rs0 = add2(rs0, e0[nt]);
                rs1 = add2(rs1, e1[nt]);
            }
            #pragma unroll
            for (int nt = 0; nt < 4; nt++) {
                int col = nt*8 + 2*q2;
                *(float2*)&sE[r0*EST_ + col]       = make_float2(lo2(e0[nt]), hi2(e0[nt]));
                *(float2*)&sE[(r0 + 8)*EST_ + col] = make_float2(lo2(e1[nt]), hi2(e1[nt]));
            }
            float rsum0 = lo2(rs0) + hi2(rs0);
            float rsum1 = lo2(rs1) + hi2(rs1);
            rsum0 += __shfl_xor_sync(0xffffffffu, rsum0, 1);
            rsum0 += __shfl_xor_sync(0xffffffffu, rsum0, 2);
            rsum1 += __shfl_xor_sync(0xffffffffu, rsum1, 1);
            rsum1 += __shfl_xor_sync(0xffffffffu, rsum1, 2);
            float rinv0 = rcpa(rsum0), rinv1 = rcpa(rsum1);
            if (q2 == 0) { sRinv[r0] = rinv0; sRinv[r0 + 8] = rinv1; }
            float m0f = (r0 < Q_) ? 1.f : 0.f;
            float m1f = (r0 + 8 < Q_) ? 1.f : 0.f;
            ull M0 = pack2(m0f, m0f), M1 = pack2(m1f, m1f);
            ull rv0p = pack2(rinv0*m0f, rinv0*m0f);
            ull rv1p = pack2(rinv1*m1f, rinv1*m1f);
            #pragma unroll
            for (int nt = 0; nt < 4; nt++) {
                ull pe = fma2(e1[nt], M1, mul2(e0[nt], M0));
                ull pa = fma2(e1[nt], rv1p, mul2(e0[nt], rv0p));
                float pex = lo2(pe), pey = hi2(pe), pax = lo2(pa), pay = hi2(pa);
                #pragma unroll
                for (int o = 4; o <= 16; o <<= 1) {
                    pex += __shfl_xor_sync(0xffffffffu, pex, o);
                    pey += __shfl_xor_sync(0xffffffffu, pey, o);
                    pax += __shfl_xor_sync(0xffffffffu, pax, o);
                    pay += __shfl_xor_sync(0xffffffffu, pay, o);
                }
                if (lane < 4) {
                    int col = nt*8 + 2*lane;
                    sPE[wid*32 + col] = pex; sPE[wid*32 + col + 1] = pey;
                    sPA[wid*32 + col] = pax; sPA[wid*32 + col + 1] = pay;
                }
            }
        } else if (u + 1 < u1) {
            int un = u + 1, ihn = un >> 6, tn = un & 63, hn = ihn & 7;
            int pn = p ^ 1;
            int idx0 = tid - 416;
            const unsigned char* bs = g_kb + (size_t)(tn*H_ + hn)*BBUF;
            unsigned bd = sbase + B_OFF + (unsigned)(pn*BBUF);
            for (int idx = idx0; idx < BBUF/16; idx += 96)
                cpa16(bd + idx*16, bs + idx*16);
            const unsigned char* vs = (const unsigned char*)(g_value + (size_t)(tn*H_ + hn)*(K_*D_));
            unsigned vd = sbase + V_OFF + (unsigned)(pn*VBUF);
            for (int idx = idx0; idx < VBUF/16; idx += 96)
                cpa16(vd + idx*16, vs + idx*16);
            CPA_COMMIT();
        }
        __syncthreads();

        // ---- phase 2: colsum reduce + coalesced writeout + pooled ----
        float pe = 0.f, pa = 0.f;
        #pragma unroll
        for (int w = 0; w < 13; w++) {
            pe += sPE[w*32 + lane];
            pa += sPA[w*32 + lane];
        }
        float yv = sYO[t*K_ + lane];
        float ta = (yv == 0.f) ? rcpa(pe) : 0.f;
        float tb = (yv == 0.f) ? 0.f : (1.f / (float)Q_);

        if (wAttn | wText) {
            float* ap = out + OUT_N + tileOff;
            float* tp = out + OUT_N + (long long)ATT_N + tileOff;
            #pragma unroll
            for (int kk = 0; kk < 4; kk++) {
                int idx = tid + kk*NT_;
                if (idx >= Q_*8) break;
                int q = idx >> 3, c = idx & 7;
                ull ev0, ev1;
                lds2(sbase + SE_OFF + (unsigned)((q*EST_ + 4*c)*4), ev0, ev1);
                if (wAttn) {
                    float rq = sRinv[q];
                    ull rv = pack2(rq, rq);
                    stg4(ap + q*K_ + 4*c, mul2(ev0, rv), mul2(ev1, rv));
                }
                if (wText) {
                    float tax = __shfl_sync(0xffffffffu, ta, 4*c);
                    float tay = __shfl_sync(0xffffffffu, ta, 4*c + 1);
                    float taz = __shfl_sync(0xffffffffu, ta, 4*c + 2);
                    float taw = __shfl_sync(0xffffffffu, ta, 4*c + 3);
                    float tbx = __shfl_sync(0xffffffffu, tb, 4*c);
                    float tby = __shfl_sync(0xffffffffu, tb, 4*c + 1);
                    float tbz = __shfl_sync(0xffffffffu, tb, 4*c + 2);
                    float tbw = __shfl_sync(0xffffffffu, tb, 4*c + 3);
                    stg4(tp + q*K_ + 4*c,
                         fma2(ev0, pack2(tax, tay), pack2(tbx, tby)),
                         fma2(ev1, pack2(taz, taw), pack2(tbz, tbw)));
                }
            }
        }
        if (wid == 13 || wid == 14) {
            int d = (wid - 13)*32 + lane;
            const float* vv = sV + p*(K_*D_);
            float a = 0.f;
            #pragma unroll
            for (int k = 0; k < 32; k++)
                a = fmaf(__shfl_sync(0xffffffffu, pa, k), vv[k*D_ + d], a);
            g_pooled[(long long)(i*T_ + t)*E_ + h*64 + d] = a * (1.f / (float)Q_);
        }
        CPA_WAIT();
        __syncthreads();
    }
}

__global__ void fc_kernel(const float* __restrict__ Wo, const float* __restrict__ bo,
                          float* __restrict__ out) {
    __shared__ float sA[64*33];
    __shared__ float sB[64*33];
    int rt = blockIdx.x * 64;
    int ct = blockIdx.y * 64;
    int tid = threadIdx.x;
    int tx = tid & 15, ty = tid >> 4;
    float acc[4][4] = {};
    float ra[8], rb[8];
    #pragma unroll
    for (int j = 0; j < 8; j++) {
        int idx = tid + j*256;
        int r = idx >> 5, kk = idx & 31;
        ra[j] = g_pooled[(rt + r)*E_ + kk];
        rb[j] = Wo[(ct + r)*E_ + kk];
    }
    for (int kc = 0; kc < E_; kc += 32) {
        #pragma unroll
        for (int j = 0; j < 8; j++) {
            int idx = tid + j*256;
            int r = idx >> 5, kk = idx & 31;
            sA[r*33 + kk] = ra[j];
            sB[r*33 + kk] = rb[j];
        }
        __syncthreads();
        if (kc + 32 < E_) {
            #pragma unroll
            for (int j = 0; j < 8; j++) {
                int idx = tid + j*256;
                int r = idx >> 5, kk = idx & 31;
                ra[j] = g_pooled[(rt + r)*E_ + kc + 32 + kk];
                rb[j] = Wo[(ct + r)*E_ + kc + 32 + kk];
            }
        }
        #pragma unroll
        for (int kk = 0; kk < 32; kk++) {
            float a[4], b[4];
            #pragma unroll
            for (int r = 0; r < 4; r++) a[r] = sA[(ty*4 + r)*33 + kk];
            #pragma unroll
            for (int c = 0; c < 4; c++) b[c] = sB[(tx*4 + c)*33 + kk];
            #pragma unroll
            for (int r = 0; r < 4; r++)
                #pragma unroll
                for (int c = 0; c < 4; c++) acc[r][c] += a[r] * b[c];
        }
        __syncthreads();
    }
    #pragma unroll
    for (int r = 0; r < 4; r++)
        #pragma unroll
        for (int c = 0; c < 4; c++)
            out[(rt + ty*4 + r)*E_ + ct + tx*4 + c] = acc[r][c] + bo[ct + tx*4 + c];
}

extern "C" void kernel_launch(void* const* d_in, const int* in_sizes, int n_in,
                              void* d_out, int out_size) {
    const float* image = (const float*)d_in[0];
    const float* text  = (const float*)d_in[1];
    const void*  mask  =                d_in[2];
    const float* Wq    = (const float*)d_in[3];
    const float* Wk    = (const float*)d_in[4];
    const float* Wv    = (const float*)d_in[5];
    const float* Wo    = (const float*)d_in[6];
    const float* bo    = (const float*)d_in[7];
    float* out = (float*)d_out;

    cudaFuncSetAttribute(attn_kernel, cudaFuncAttributeMaxDynamicSharedMemorySize, SMEM_ATTN);

    mask_kernel<<<1, 256>>>(mask);
    proj_all<<<904, 256>>>(image, text, Wq, Wk, Wv);
    kprep_kernel<<<T_*H_, 256>>>();

    int wAttn = out_size >= (OUT_N + ATT_N);
    int wText = out_size >= (OUT_N + 2*ATT_N);
    attn_kernel<<<NCTA_, NT_, SMEM_ATTN>>>(out, wAttn, wText);

    if (out_size >= OUT_N)
        fc_kernel<<<dim3(16, 8), 256>>>(Wo, bo, out);
}

// round 15
// speedup vs baseline: 1.0656x; 1.0420x over previous
#include <cuda_runtime.h>
#include <cuda_bf16.h>
#include <math.h>
#include <cstdint>

#define I_ 16
#define T_ 64
#define Q_ 196
#define K_ 32
#define E_ 512
#define H_ 8
#define D_ 64
#define NT_ 512
#define NCTA_ 148
#define NU_ (I_*H_*T_)

#define OUT_N   (I_*T_*E_)
#define ATT_N   (I_*T_*H_*Q_*K_)
#define SC2_    ((float)(0.044194173824159216*1.4426950408889634))

#define SA_  136
#define MR_  208
#define EST_ 36
#define BBUF (K_*SA_*2)                 // 8704
#define VBUF (K_*D_*4)                  // 8192
#define ABYTES (MR_*SA_*2)              // 56576
#define SEBUF (MR_*EST_*4)              // 29952

#define A_OFF    0
#define SE_OFF   56576                  // 2 x 29952
#define YO_OFF   116480                 // 8192
#define B_OFF    124672                 // 2 x 8704
#define V_OFF    142080                 // 3 x 8192
#define RINV_OFF 166656                 // 2 x 832 (pad 1664)
#define PE_OFF   168320                 // 2 x 2048
#define PA_OFF   172416                 // 2 x 2048
#define SMEM_ATTN 176512

typedef unsigned long long ull;

__device__ float g_query[I_*H_*Q_*D_];
__device__ float g_key  [T_*H_*K_*D_];
__device__ float g_value[T_*H_*K_*D_];
__device__ float g_pooled[I_*T_*E_];
__device__ float g_maskf[T_*K_];
__device__ unsigned char g_kb[(size_t)T_*H_*BBUF];

__device__ __forceinline__ unsigned smem_u32(const void* p) {
    unsigned a;
    asm("{ .reg .u64 t; cvta.to.shared.u64 t, %1; cvt.u32.u64 %0, t; }" : "=r"(a) : "l"(p));
    return a;
}
__device__ __forceinline__ ull fma2(ull a, ull b, ull c) {
    ull d; asm("fma.rn.f32x2 %0, %1, %2, %3;" : "=l"(d) : "l"(a), "l"(b), "l"(c)); return d;
}
__device__ __forceinline__ ull mul2(ull a, ull b) {
    ull d; asm("mul.rn.f32x2 %0, %1, %2;" : "=l"(d) : "l"(a), "l"(b)); return d;
}
__device__ __forceinline__ ull add2(ull a, ull b) {
    ull d; asm("add.rn.f32x2 %0, %1, %2;" : "=l"(d) : "l"(a), "l"(b)); return d;
}
__device__ __forceinline__ ull pack2(float x, float y) {
    ull d; asm("mov.b64 %0, {%1, %2};" : "=l"(d) : "f"(x), "f"(y)); return d;
}
__device__ __forceinline__ float lo2(ull a) { return __uint_as_float((unsigned)a); }
__device__ __forceinline__ float hi2(ull a) { return __uint_as_float((unsigned)(a >> 32)); }
__device__ __forceinline__ float ex2(float x) {
    float y; asm("ex2.approx.f32 %0, %1;" : "=f"(y) : "f"(x)); return y;
}
__device__ __forceinline__ float rcpa(float x) {
    float y; asm("rcp.approx.f32 %0, %1;" : "=f"(y) : "f"(x)); return y;
}
__device__ __forceinline__ ull lds1(unsigned a) {
    ull x; asm volatile("ld.shared.b64 %0, [%1];" : "=l"(x) : "r"(a)); return x;
}
__device__ __forceinline__ void lds2(unsigned a, ull& x, ull& y) {
    asm volatile("ld.shared.v2.b64 {%0,%1}, [%2];" : "=l"(x), "=l"(y) : "r"(a));
}
__device__ __forceinline__ void stg4(float* p, ull a, ull b) {
    asm volatile("{ .reg .f32 x,y,z,w; mov.b64 {x,y}, %1; mov.b64 {z,w}, %2;"
                 " st.global.v4.f32 [%0], {x,y,z,w}; }" :: "l"(p), "l"(a), "l"(b) : "memory");
}
__device__ __forceinline__ void cpa16(unsigned dst, const void* src) {
    asm volatile("cp.async.cg.shared.global [%0], [%1], 16;" :: "r"(dst), "l"(src) : "memory");
}
#define CPA_COMMIT() asm volatile("cp.async.commit_group;" ::: "memory")
#define CPA_WAIT()   asm volatile("cp.async.wait_group 0;" ::: "memory")
__device__ __forceinline__ void ldm_x4(unsigned a, unsigned& r0, unsigned& r1,
                                       unsigned& r2, unsigned& r3) {
    asm volatile("ldmatrix.sync.aligned.m8n8.x4.shared.b16 {%0,%1,%2,%3}, [%4];"
                 : "=r"(r0), "=r"(r1), "=r"(r2), "=r"(r3) : "r"(a));
}
__device__ __forceinline__ void ldm_x2(unsigned a, unsigned& r0, unsigned& r1) {
    asm volatile("ldmatrix.sync.aligned.m8n8.x2.shared.b16 {%0,%1}, [%2];"
                 : "=r"(r0), "=r"(r1) : "r"(a));
}
__device__ __forceinline__ void mma_bf16(float* c, const unsigned* a, unsigned b0, unsigned b1) {
    asm volatile("mma.sync.aligned.m16n8k16.row.col.f32.bf16.bf16.f32 "
                 "{%0,%1,%2,%3}, {%4,%5,%6,%7}, {%8,%9}, {%0,%1,%2,%3};"
                 : "+f"(c[0]), "+f"(c[1]), "+f"(c[2]), "+f"(c[3])
                 : "r"(a[0]), "r"(a[1]), "r"(a[2]), "r"(a[3]), "r"(b0), "r"(b1));
}

__global__ void mask_kernel(const void* mp) {
    __shared__ int mode;
    if (threadIdx.x == 0) {
        const unsigned char* b = (const unsigned char*)mp;
        int c3f = 0, cnz = 0;
        for (int k = 0; k < 512; k++) {
            if (b[4*k+3] == 0x3F) c3f++;
            if (b[4*k+1] | b[4*k+2]) cnz++;
        }
        mode = (c3f > 8) ? 2 : ((cnz > 8) ? 0 : 1);
    }
    __syncthreads();
    int m = mode;
    for (int idx = threadIdx.x; idx < T_*K_; idx += blockDim.x) {
        float v;
        if (m == 0)      v = ((const unsigned char*)mp)[idx] ? 1.f : 0.f;
        else if (m == 1) v = ((const int*)mp)[idx] ? 1.f : 0.f;
        else             v = (((const float*)mp)[idx] != 0.f) ? 1.f : 0.f;
        g_maskf[idx] = v;
    }
}

__global__ void proj_all(const float* __restrict__ image, const float* __restrict__ text,
                         const float* __restrict__ Wq, const float* __restrict__ Wk,
                         const float* __restrict__ Wv) {
    __shared__ float sA[64*33];
    __shared__ float sB[64*33];
    int bid = blockIdx.x;
    int which, h, rb;
    const float *X, *W;
    float* Y;
    if (bid < 392)      { which = 0; h = bid/49;       rb = bid%49;       X = image; W = Wq; Y = g_query; }
    else if (bid < 648) { which = 1; h = (bid-392)/32; rb = (bid-392)%32; X = text;  W = Wk; Y = g_key;   }
    else                { which = 2; h = (bid-648)/32; rb = (bid-648)%32; X = text;  W = Wv; Y = g_value; }
    int r0 = rb * 64;
    int tid = threadIdx.x;
    int tx = tid & 15, ty = tid >> 4;
    float acc[4][4] = {};
    #pragma unroll
    for (int kc = 0; kc < 64; kc += 32) {
        for (int idx = tid; idx < 2048; idx += 256) {
            int r = idx >> 5, kk = idx & 31;
            sA[r*33 + kk] = X[(r0 + r)*E_ + h*64 + kc + kk];
            sB[r*33 + kk] = W[r*64 + kc + kk];
        }
        __syncthreads();
        #pragma unroll
        for (int kk = 0; kk < 32; kk++) {
            float a[4], b[4];
            #pragma unroll
            for (int r = 0; r < 4; r++) a[r] = sA[(ty*4 + r)*33 + kk];
            #pragma unroll
            for (int c = 0; c < 4; c++) b[c] = sB[(tx*4 + c)*33 + kk];
            #pragma unroll
            for (int r = 0; r < 4; r++)
                #pragma unroll
                for (int c = 0; c < 4; c++) acc[r][c] += a[r] * b[c];
        }
        __syncthreads();
    }
    #pragma unroll
    for (int r = 0; r < 4; r++) {
        int row = r0 + ty*4 + r;
        long long obase;
        if (which == 0) { int i = row / Q_, q = row % Q_; obase = ((long long)(i*H_ + h)*Q_ + q)*64; }
        else            { int t = row >> 5, k = row & 31; obase = ((long long)(t*H_ + h)*K_ + k)*64; }
        #pragma unroll
        for (int c = 0; c < 4; c++)
            Y[obase + tx*4 + c] = acc[r][c];
    }
}

__global__ void kprep_kernel() {
    int th = blockIdx.x, tid = threadIdx.x;
    const float* Kg = g_key + (size_t)th*(K_*D_);
    unsigned char* B = g_kb + (size_t)th*BBUF;
    for (int idx = tid; idx < (K_*D_)/2; idx += 256) {
        int k = idx >> 5, d2 = (idx & 31)*2;
        float2 x = *(const float2*)&Kg[k*64 + d2];
        __nv_bfloat162 hi = __floats2bfloat162_rn(x.x, x.y);
        float2 hf = __bfloat1622float2(hi);
        __nv_bfloat162 lo = __floats2bfloat162_rn(x.x - hf.x, x.y - hf.y);
        *(__nv_bfloat162*)(B + (k*SA_ + d2)*2)      = hi;
        *(__nv_bfloat162*)(B + (k*SA_ + 64 + d2)*2) = lo;
    }
}

__global__ void __launch_bounds__(NT_, 1)
attn_kernel(float* __restrict__ out, int wAttn, int wText) {
    extern __shared__ unsigned char smem[];
    unsigned sbase = smem_u32(smem);
    float* sYO   = (float*)(smem + YO_OFF);
    float* sV    = (float*)(smem + V_OFF);
    float* sE    = (float*)(smem + SE_OFF);
    float* sRinv = (float*)(smem + RINV_OFF);
    float* sPE   = (float*)(smem + PE_OFF);
    float* sPA   = (float*)(smem + PA_OFF);

    int tid = threadIdx.x, lane = tid & 31, wid = tid >> 5;
    int bid = blockIdx.x;
    int u0 = (bid * NU_) / NCTA_;
    int u1 = ((bid + 1) * NU_) / NCTA_;

    for (int idx = tid; idx < T_*K_; idx += NT_) {
        float m = g_maskf[idx];
        sYO[idx] = (m != 0.f) ? 0.f : -1e30f;
    }
    {
        int ihs = u0 >> 6, ts = u0 & 63, hs = ihs & 7;
        const float4* bs = (const float4*)(g_kb + (size_t)(ts*H_ + hs)*BBUF);
        float4* bd = (float4*)(smem + B_OFF);
        for (int idx = tid; idx < BBUF/16; idx += NT_) bd[idx] = bs[idx];
        const float4* vs = (const float4*)(g_value + (size_t)(ts*H_ + hs)*(K_*D_));
        float4* vd = (float4*)sV;
        for (int idx = tid; idx < (K_*D_)/4; idx += NT_) vd[idx] = vs[idx];
    }
    __syncthreads();

    unsigned ahi[4][4], alo[4][4];
    int curih = -1;
    const ull S2 = pack2(SC2_, SC2_);
    int g = lane >> 2, q2 = lane & 3;

    for (int u = u0; u < u1; u++) {
        int ih = u >> 6, t = u & 63;
        int h = ih & 7, i = ih >> 3;
        int p = (u - u0) & 1;

        if (ih != curih) {
            unsigned* z = (unsigned*)(smem + A_OFF);
            for (int idx = tid; idx < ABYTES/4; idx += NT_) z[idx] = 0u;
            __syncthreads();
            const float* Qg = g_query + (size_t)ih*(Q_*D_);
            unsigned char* A = smem + A_OFF;
            for (int idx = tid; idx < (Q_*D_)/2; idx += NT_) {
                int q = idx >> 5, d2 = (idx & 31)*2;
                float2 x = *(const float2*)&Qg[q*64 + d2];
                __nv_bfloat162 hi = __floats2bfloat162_rn(x.x, x.y);
                float2 hf = __bfloat1622float2(hi);
                __nv_bfloat162 lo = __floats2bfloat162_rn(x.x - hf.x, x.y - hf.y);
                *(__nv_bfloat162*)(A + (q*SA_ + d2)*2)      = hi;
                *(__nv_bfloat162*)(A + (q*SA_ + 64 + d2)*2) = lo;
            }
            __syncthreads();
            if (wid < 13) {
                int lrow = lane & 15;
                int lcol = (lane < 16) ? 0 : 8;
                #pragma unroll
                for (int ks = 0; ks < 4; ks++) {
                    unsigned a0 = sbase + A_OFF + (unsigned)(((wid*16 + lrow)*SA_ + ks*16 + lcol)*2);
                    ldm_x4(a0, ahi[ks][0], ahi[ks][1], ahi[ks][2], ahi[ks][3]);
                    ldm_x4(a0 + 128, alo[ks][0], alo[ks][1], alo[ks][2], alo[ks][3]);
                }
            }
            curih = ih;
        }

        // ---- single phase: MMA(t) / prefetch(t+1), then writeout(t-1) ----
        if (wid < 13) {
            unsigned sBb = sbase + B_OFF + (unsigned)(p*BBUF);
            int ln = lane & 15;
            int bn = ln & 7;
            int bc = (ln < 8) ? 0 : 8;
            int r0 = wid*16 + g;
            unsigned yoT = sbase + YO_OFF + (unsigned)(t*128);
            float c[4][4] = {};
            #pragma unroll
            for (int ks = 0; ks < 4; ks++) {
                unsigned bh0[4], bh1[4], bl0[4], bl1[4];
                #pragma unroll
                for (int nt = 0; nt < 4; nt++) {
                    unsigned ab = sBb + (unsigned)(((nt*8 + bn)*SA_ + ks*16 + bc)*2);
                    ldm_x2(ab, bh0[nt], bh1[nt]);
                    ldm_x2(ab + 128, bl0[nt], bl1[nt]);
                }
                #pragma unroll
                for (int nt = 0; nt < 4; nt++) {
                    mma_bf16(c[nt], ahi[ks], bh0[nt], bh1[nt]);
                    mma_bf16(c[nt], alo[ks], bh0[nt], bh1[nt]);
                    mma_bf16(c[nt], ahi[ks], bl0[nt], bl1[nt]);
                }
            }
            ull e0[4], e1[4];
            ull rs0 = pack2(0.f, 0.f), rs1 = pack2(0.f, 0.f);
            #pragma unroll
            for (int nt = 0; nt < 4; nt++) {
                ull yo = lds1(yoT + (unsigned)((nt*8 + 2*q2)*4));
                ull v0 = fma2(pack2(c[nt][0], c[nt][1]), S2, yo);
                ull v1 = fma2(pack2(c[nt][2], c[nt][3]), S2, yo);
                e0[nt] = pack2(ex2(lo2(v0)), ex2(hi2(v0)));
                e1[nt] = pack2(ex2(lo2(v1)), ex2(hi2(v1)));
                rs0 = add2(rs0, e0[nt]);
                rs1 = add2(rs1, e1[nt]);
            }
            float* sEp = (float*)(smem + SE_OFF + p*SEBUF);
            #pragma unroll
            for (int nt = 0; nt < 4; nt++) {
                int col = nt*8 + 2*q2;
                *(float2*)&sEp[r0*EST_ + col]       = make_float2(lo2(e0[nt]), hi2(e0[nt]));
                *(float2*)&sEp[(r0 + 8)*EST_ + col] = make_float2(lo2(e1[nt]), hi2(e1[nt]));
            }
            float rsum0 = lo2(rs0) + hi2(rs0);
            float rsum1 = lo2(rs1) + hi2(rs1);
            rsum0 += __shfl_xor_sync(0xffffffffu, rsum0, 1);
            rsum0 += __shfl_xor_sync(0xffffffffu, rsum0, 2);
            rsum1 += __shfl_xor_sync(0xffffffffu, rsum1, 1);
            rsum1 += __shfl_xor_sync(0xffffffffu, rsum1, 2);
            float rinv0 = rcpa(rsum0), rinv1 = rcpa(rsum1);
            if (q2 == 0) { sRinv[p*208 + r0] = rinv0; sRinv[p*208 + r0 + 8] = rinv1; }
            float m0f = (r0 < Q_) ? 1.f : 0.f;
            float m1f = (r0 + 8 < Q_) ? 1.f : 0.f;
            ull M0 = pack2(m0f, m0f), M1 = pack2(m1f, m1f);
            ull rv0p = pack2(rinv0*m0f, rinv0*m0f);
            ull rv1p = pack2(rinv1*m1f, rinv1*m1f);
            #pragma unroll
            for (int nt = 0; nt < 4; nt++) {
                ull pe2 = fma2(e1[nt], M1, mul2(e0[nt], M0));
                ull pa2 = fma2(e1[nt], rv1p, mul2(e0[nt], rv0p));
                float pex = lo2(pe2), pey = hi2(pe2), pax = lo2(pa2), pay = hi2(pa2);
                #pragma unroll
                for (int o = 4; o <= 16; o <<= 1) {
                    pex += __shfl_xor_sync(0xffffffffu, pex, o);
                    pey += __shfl_xor_sync(0xffffffffu, pey, o);
                    pax += __shfl_xor_sync(0xffffffffu, pax, o);
                    pay += __shfl_xor_sync(0xffffffffu, pay, o);
                }
                if (lane < 4) {
                    int col = nt*8 + 2*lane;
                    sPE[p*512 + wid*32 + col] = pex; sPE[p*512 + wid*32 + col + 1] = pey;
                    sPA[p*512 + wid*32 + col] = pax; sPA[p*512 + wid*32 + col + 1] = pay;
                }
            }
        } else if (u + 1 < u1) {
            int un = u + 1, tn = un & 63, hn = (un >> 6) & 7;
            int pn = p ^ 1, vn = (un - u0) % 3;
            int idx0 = tid - 416;
            const unsigned char* bs = g_kb + (size_t)(tn*H_ + hn)*BBUF;
            unsigned bd = sbase + B_OFF + (unsigned)(pn*BBUF);
            for (int idx = idx0; idx < BBUF/16; idx += 96)
                cpa16(bd + idx*16, bs + idx*16);
            const unsigned char* vs = (const unsigned char*)(g_value + (size_t)(tn*H_ + hn)*(K_*D_));
            unsigned vd = sbase + V_OFF + (unsigned)(vn*VBUF);
            for (int idx = idx0; idx < VBUF/16; idx += 96)
                cpa16(vd + idx*16, vs + idx*16);
            CPA_COMMIT();
        }

        // ---- writeout for previous unit (from p^1 buffers) ----
        if (u > u0) {
            int pu = u - 1;
            int pt = pu & 63, pih = pu >> 6;
            int ph = pih & 7, pi = pih >> 3;
            int pp = (pu - u0) & 1;
            int pv = (pu - u0) % 3;
            long long pOff = ((long long)(pi*T_ + pt)*H_ + ph) * (Q_*K_);
            float pe = 0.f, pa = 0.f;
            #pragma unroll
            for (int w = 0; w < 13; w++) {
                pe += sPE[pp*512 + w*32 + lane];
                pa += sPA[pp*512 + w*32 + lane];
            }
            float yv = sYO[pt*K_ + lane];
            float ta = (yv == 0.f) ? rcpa(pe) : 0.f;
            float tb = (yv == 0.f) ? 0.f : (1.f / (float)Q_);
            if (wAttn | wText) {
                float* ap = out + OUT_N + pOff;
                float* tp = out + OUT_N + (long long)ATT_N + pOff;
                unsigned seb = sbase + SE_OFF + (unsigned)(pp*SEBUF);
                #pragma unroll
                for (int kk = 0; kk < 4; kk++) {
                    int idx = tid + kk*NT_;
                    if (idx >= Q_*8) break;
                    int q = idx >> 3, c = idx & 7;
                    ull ev0, ev1;
                    lds2(seb + (unsigned)((q*EST_ + 4*c)*4), ev0, ev1);
                    if (wAttn) {
                        float rq = sRinv[pp*208 + q];
                        ull rv = pack2(rq, rq);
                        stg4(ap + q*K_ + 4*c, mul2(ev0, rv), mul2(ev1, rv));
                    }
                    if (wText) {
                        float tax = __shfl_sync(0xffffffffu, ta, 4*c);
                        float tay = __shfl_sync(0xffffffffu, ta, 4*c + 1);
                        float taz = __shfl_sync(0xffffffffu, ta, 4*c + 2);
                        float taw = __shfl_sync(0xffffffffu, ta, 4*c + 3);
                        float tbx = __shfl_sync(0xffffffffu, tb, 4*c);
                        float tby = __shfl_sync(0xffffffffu, tb, 4*c + 1);
                        float tbz = __shfl_sync(0xffffffffu, tb, 4*c + 2);
                        float tbw = __shfl_sync(0xffffffffu, tb, 4*c + 3);
                        stg4(tp + q*K_ + 4*c,
                             fma2(ev0, pack2(tax, tay), pack2(tbx, tby)),
                             fma2(ev1, pack2(taz, taw), pack2(tbz, tbw)));
                    }
                }
            }
            if (wid == 13 || wid == 14) {
                int d = (wid - 13)*32 + lane;
                const float* vv = sV + pv*(K_*D_);
                float a = 0.f;
                #pragma unroll
                for (int k = 0; k < 32; k++)
                    a = fmaf(__shfl_sync(0xffffffffu, pa, k), vv[k*D_ + d], a);
                g_pooled[(long long)(pi*T_ + pt)*E_ + ph*64 + d] = a * (1.f / (float)Q_);
            }
        }
        if (wid >= 13) CPA_WAIT();
        __syncthreads();
    }

    // ---- drain: writeout for last unit ----
    {
        int pu = u1 - 1;
        int pt = pu & 63, pih = pu >> 6;
        int ph = pih & 7, pi = pih >> 3;
        int pp = (pu - u0) & 1;
        int pv = (pu - u0) % 3;
        long long pOff = ((long long)(pi*T_ + pt)*H_ + ph) * (Q_*K_);
        float pe = 0.f, pa = 0.f;
        #pragma unroll
        for (int w = 0; w < 13; w++) {
            pe += sPE[pp*512 + w*32 + lane];
            pa += sPA[pp*512 + w*32 + lane];
        }
        float yv = sYO[pt*K_ + lane];
        float ta = (yv == 0.f) ? rcpa(pe) : 0.f;
        float tb = (yv == 0.f) ? 0.f : (1.f / (float)Q_);
        if (wAttn | wText) {
            float* ap = out + OUT_N + pOff;
            float* tp = out + OUT_N + (long long)ATT_N + pOff;
            unsigned seb = sbase + SE_OFF + (unsigned)(pp*SEBUF);
            #pragma unroll
            for (int kk = 0; kk < 4; kk++) {
                int idx = tid + kk*NT_;
                if (idx >= Q_*8) break;
                int q = idx >> 3, c = idx & 7;
                ull ev0, ev1;
                lds2(seb + (unsigned)((q*EST_ + 4*c)*4), ev0, ev1);
                if (wAttn) {
                    float rq = sRinv[pp*208 + q];
                    ull rv = pack2(rq, rq);
                    stg4(ap + q*K_ + 4*c, mul2(ev0, rv), mul2(ev1, rv));
                }
                if (wText) {
                    float tax = __shfl_sync(0xffffffffu, ta, 4*c);
                    float tay = __shfl_sync(0xffffffffu, ta, 4*c + 1);
                    float taz = __shfl_sync(0xffffffffu, ta, 4*c + 2);
                    float taw = __shfl_sync(0xffffffffu, ta, 4*c + 3);
                    float tbx = __shfl_sync(0xffffffffu, tb, 4*c);
                    float tby = __shfl_sync(0xffffffffu, tb, 4*c + 1);
                    float tbz = __shfl_sync(0xffffffffu, tb, 4*c + 2);
                    float tbw = __shfl_sync(0xffffffffu, tb, 4*c + 3);
                    stg4(tp + q*K_ + 4*c,
                         fma2(ev0, pack2(tax, tay), pack2(tbx, tby)),
                         fma2(ev1, pack2(taz, taw), pack2(tbz, tbw)));
                }
            }
        }
        if (wid == 13 || wid == 14) {
            int d = (wid - 13)*32 + lane;
            const float* vv = sV + pv*(K_*D_);
            float a = 0.f;
            #pragma unroll
            for (int k = 0; k < 32; k++)
                a = fmaf(__shfl_sync(0xffffffffu, pa, k), vv[k*D_ + d], a);
            g_pooled[(long long)(pi*T_ + pt)*E_ + ph*64 + d] = a * (1.f / (float)Q_);
        }
    }
}

// fc: 32-row tiles, grid (32, 8) = 256 CTAs for ~2 CTAs/SM
__global__ void __launch_bounds__(256, 2)
fc_kernel(const float* __restrict__ Wo, const float* __restrict__ bo,
          float* __restrict__ out) {
    __shared__ float sA[32*33];
    __shared__ float sB[64*33];
    int rt = blockIdx.x * 32;
    int ct = blockIdx.y * 64;
    int tid = threadIdx.x;
    int tx = tid & 15, ty = tid >> 4;
    float acc[2][4] = {};
    float ra[4], rb[8];
    #pragma unroll
    for (int j = 0; j < 4; j++) {
        int idx = tid + j*256;
        int r = idx >> 5, kk = idx & 31;
        ra[j] = g_pooled[(rt + r)*E_ + kk];
    }
    #pragma unroll
    for (int j = 0; j < 8; j++) {
        int idx = tid + j*256;
        int r = idx >> 5, kk = idx & 31;
        rb[j] = Wo[(ct + r)*E_ + kk];
    }
    for (int kc = 0; kc < E_; kc += 32) {
        #pragma unroll
        for (int j = 0; j < 4; j++) {
            int idx = tid + j*256;
            sA[(idx >> 5)*33 + (idx & 31)] = ra[j];
        }
        #pragma unroll
        for (int j = 0; j < 8; j++) {
            int idx = tid + j*256;
            sB[(idx >> 5)*33 + (idx & 31)] = rb[j];
        }
        __syncthreads();
        if (kc + 32 < E_) {
            #pragma unroll
            for (int j = 0; j < 4; j++) {
                int idx = tid + j*256;
                ra[j] = g_pooled[(rt + (idx >> 5))*E_ + kc + 32 + (idx & 31)];
            }
            #pragma unroll
            for (int j = 0; j < 8; j++) {
                int idx = tid + j*256;
                rb[j] = Wo[(ct + (idx >> 5))*E_ + kc + 32 + (idx & 31)];
            }
        }
        #pragma unroll
        for (int kk = 0; kk < 32; kk++) {
            float a[2], b[4];
            #pragma unroll
            for (int r = 0; r < 2; r++) a[r] = sA[(ty*2 + r)*33 + kk];
            #pragma unroll
            for (int c = 0; c < 4; c++) b[c] = sB[(tx*4 + c)*33 + kk];
            #pragma unroll
            for (int r = 0; r < 2; r++)
                #pragma unroll
                for (int c = 0; c < 4; c++) acc[r][c] += a[r] * b[c];
        }
        __syncthreads();
    }
    #pragma unroll
    for (int r = 0; r < 2; r++)
        #pragma unroll
        for (int c = 0; c < 4; c++)
            out[(rt + ty*2 + r)*E_ + ct + tx*4 + c] = acc[r][c] + bo[ct + tx*4 + c];
}

extern "C" void kernel_launch(void* const* d_in, const int* in_sizes, int n_in,
                              void* d_out, int out_size) {
    const float* image = (const float*)d_in[0];
    const float* text  = (const float*)d_in[1];
    const void*  mask  =                d_in[2];
    const float* Wq    = (const float*)d_in[3];
    const float* Wk    = (const float*)d_in[4];
    const float* Wv    = (const float*)d_in[5];
    const float* Wo    = (const float*)d_in[6];
    const float* bo    = (const float*)d_in[7];
    float* out = (float*)d_out;

    cudaFuncSetAttribute(attn_kernel, cudaFuncAttributeMaxDynamicSharedMemorySize, SMEM_ATTN);

    mask_kernel<<<1, 256>>>(mask);
    proj_all<<<904, 256>>>(image, text, Wq, Wk, Wv);
    kprep_kernel<<<T_*H_, 256>>>();

    int wAttn = out_size >= (OUT_N + ATT_N);
    int wText = out_size >= (OUT_N + 2*ATT_N);
    attn_kernel<<<NCTA_, NT_, SMEM_ATTN>>>(out, wAttn, wText);

    if (out_size >= OUT_N)
        fc_kernel<<<dim3(32, 8), 256>>>(Wo, bo, out);
}

// round 16
// speedup vs baseline: 1.0786x; 1.0122x over previous
#include <cuda_runtime.h>
#include <cuda_bf16.h>
#include <math.h>
#include <cstdint>

#define I_ 16
#define T_ 64
#define Q_ 196
#define K_ 32
#define E_ 512
#define H_ 8
#define D_ 64
#define NT_ 512
#define NCTA_ 148
#define NU_ (I_*H_*T_)

#define OUT_N   (I_*T_*E_)
#define ATT_N   (I_*T_*H_*Q_*K_)
#define SC2_    ((float)(0.044194173824159216*1.4426950408889634))

#define SA_  136
#define MR_  208
#define EST_ 36
#define BBUF (K_*SA_*2)                 // 8704
#define VBUF (K_*D_*4)                  // 8192
#define ABYTES (MR_*SA_*2)              // 56576
#define SEBUF (MR_*EST_*4)              // 29952

#define A_OFF    0
#define SE_OFF   56576
#define YO_OFF   116480
#define B_OFF    124672
#define V_OFF    142080
#define RINV_OFF 166656
#define PE_OFF   168320
#define PA_OFF   172416
#define SMEM_ATTN 176512

typedef unsigned long long ull;

__device__ float g_value[T_*H_*K_*D_];
__device__ float g_pooled[I_*T_*E_];
__device__ float g_maskf[T_*K_];
__device__ __nv_bfloat16 g_qb[(size_t)I_*H_*MR_*SA_];   // pre-split A tiles, zero-padded
__device__ __nv_bfloat16 g_kb[(size_t)T_*H_*K_*SA_];    // pre-split B tiles

__device__ __forceinline__ unsigned smem_u32(const void* p) {
    unsigned a;
    asm("{ .reg .u64 t; cvta.to.shared.u64 t, %1; cvt.u32.u64 %0, t; }" : "=r"(a) : "l"(p));
    return a;
}
__device__ __forceinline__ ull fma2(ull a, ull b, ull c) {
    ull d; asm("fma.rn.f32x2 %0, %1, %2, %3;" : "=l"(d) : "l"(a), "l"(b), "l"(c)); return d;
}
__device__ __forceinline__ ull mul2(ull a, ull b) {
    ull d; asm("mul.rn.f32x2 %0, %1, %2;" : "=l"(d) : "l"(a), "l"(b)); return d;
}
__device__ __forceinline__ ull add2(ull a, ull b) {
    ull d; asm("add.rn.f32x2 %0, %1, %2;" : "=l"(d) : "l"(a), "l"(b)); return d;
}
__device__ __forceinline__ ull pack2(float x, float y) {
    ull d; asm("mov.b64 %0, {%1, %2};" : "=l"(d) : "f"(x), "f"(y)); return d;
}
__device__ __forceinline__ float lo2(ull a) { return __uint_as_float((unsigned)a); }
__device__ __forceinline__ float hi2(ull a) { return __uint_as_float((unsigned)(a >> 32)); }
__device__ __forceinline__ float ex2(float x) {
    float y; asm("ex2.approx.f32 %0, %1;" : "=f"(y) : "f"(x)); return y;
}
__device__ __forceinline__ float rcpa(float x) {
    float y; asm("rcp.approx.f32 %0, %1;" : "=f"(y) : "f"(x)); return y;
}
__device__ __forceinline__ ull lds1(unsigned a) {
    ull x; asm volatile("ld.shared.b64 %0, [%1];" : "=l"(x) : "r"(a)); return x;
}
__device__ __forceinline__ void lds2(unsigned a, ull& x, ull& y) {
    asm volatile("ld.shared.v2.b64 {%0,%1}, [%2];" : "=l"(x), "=l"(y) : "r"(a));
}
__device__ __forceinline__ void stg4(float* p, ull a, ull b) {
    asm volatile("{ .reg .f32 x,y,z,w; mov.b64 {x,y}, %1; mov.b64 {z,w}, %2;"
                 " st.global.v4.f32 [%0], {x,y,z,w}; }" :: "l"(p), "l"(a), "l"(b) : "memory");
}
__device__ __forceinline__ void cpa16(unsigned dst, const void* src) {
    asm volatile("cp.async.cg.shared.global [%0], [%1], 16;" :: "r"(dst), "l"(src) : "memory");
}
#define CPA_COMMIT() asm volatile("cp.async.commit_group;" ::: "memory")
#define CPA_WAIT()   asm volatile("cp.async.wait_group 0;" ::: "memory")
__device__ __forceinline__ void ldm_x4(unsigned a, unsigned& r0, unsigned& r1,
                                       unsigned& r2, unsigned& r3) {
    asm volatile("ldmatrix.sync.aligned.m8n8.x4.shared.b16 {%0,%1,%2,%3}, [%4];"
                 : "=r"(r0), "=r"(r1), "=r"(r2), "=r"(r3) : "r"(a));
}
__device__ __forceinline__ void mma_bf16(float* c, const unsigned* a, unsigned b0, unsigned b1) {
    asm volatile("mma.sync.aligned.m16n8k16.row.col.f32.bf16.bf16.f32 "
                 "{%0,%1,%2,%3}, {%4,%5,%6,%7}, {%8,%9}, {%0,%1,%2,%3};"
                 : "+f"(c[0]), "+f"(c[1]), "+f"(c[2]), "+f"(c[3])
                 : "r"(a[0]), "r"(a[1]), "r"(a[2]), "r"(a[3]), "r"(b0), "r"(b1));
}

// ---- fused prep: QKV projections (split-bf16 outputs) + mask, one launch ----
__global__ void prep_all(const float* __restrict__ image, const float* __restrict__ text,
                         const float* __restrict__ Wq, const float* __restrict__ Wk,
                         const float* __restrict__ Wv, const void* mp) {
    int bid = blockIdx.x;
    int tid = threadIdx.x;
    if (bid == 904) {                           // mask conversion CTA
        __shared__ int mode;
        if (tid == 0) {
            const unsigned char* b = (const unsigned char*)mp;
            int c3f = 0, cnz = 0;
            for (int k = 0; k < 512; k++) {
                if (b[4*k+3] == 0x3F) c3f++;
                if (b[4*k+1] | b[4*k+2]) cnz++;
            }
            mode = (c3f > 8) ? 2 : ((cnz > 8) ? 0 : 1);
        }
        __syncthreads();
        int m = mode;
        for (int idx = tid; idx < T_*K_; idx += blockDim.x) {
            float v;
            if (m == 0)      v = ((const unsigned char*)mp)[idx] ? 1.f : 0.f;
            else if (m == 1) v = ((const int*)mp)[idx] ? 1.f : 0.f;
            else             v = (((const float*)mp)[idx] != 0.f) ? 1.f : 0.f;
            g_maskf[idx] = v;
        }
        return;
    }

    __shared__ float sA[64*33];
    __shared__ float sB[64*33];
    int which, h, rb;
    const float *X, *W;
    if (bid < 392)      { which = 0; h = bid/49;       rb = bid%49;       X = image; W = Wq; }
    else if (bid < 648) { which = 1; h = (bid-392)/32; rb = (bid-392)%32; X = text;  W = Wk; }
    else                { which = 2; h = (bid-648)/32; rb = (bid-648)%32; X = text;  W = Wv; }
    int r0 = rb * 64;
    int tx = tid & 15, ty = tid >> 4;
    float acc[4][4] = {};
    #pragma unroll
    for (int kc = 0; kc < 64; kc += 32) {
        for (int idx = tid; idx < 2048; idx += 256) {
            int r = idx >> 5, kk = idx & 31;
            sA[r*33 + kk] = X[(r0 + r)*E_ + h*64 + kc + kk];
            sB[r*33 + kk] = W[r*64 + kc + kk];
        }
        __syncthreads();
        #pragma unroll
        for (int kk = 0; kk < 32; kk++) {
            float a[4], b[4];
            #pragma unroll
            for (int r = 0; r < 4; r++) a[r] = sA[(ty*4 + r)*33 + kk];
            #pragma unroll
            for (int c = 0; c < 4; c++) b[c] = sB[(tx*4 + c)*33 + kk];
            #pragma unroll
            for (int r = 0; r < 4; r++)
                #pragma unroll
                for (int c = 0; c < 4; c++) acc[r][c] += a[r] * b[c];
        }
        __syncthreads();
    }
    int d = tx*4;
    #pragma unroll
    for (int r = 0; r < 4; r++) {
        int row = r0 + ty*4 + r;
        if (which == 2) {                       // V: fp32
            int t = row >> 5, k = row & 31;
            long long ob = ((long long)(t*H_ + h)*K_ + k)*64 + d;
            #pragma unroll
            for (int c = 0; c < 4; c++) g_value[ob + c] = acc[r][c];
        } else {                                // Q/K: split bf16 [hi|lo], stride SA_
            __nv_bfloat16* dst;
            if (which == 0) {
                int i = row / Q_, q = row % Q_;
                dst = g_qb + ((size_t)(i*H_ + h)*MR_ + q)*SA_;
            } else {
                int t = row >> 5, k = row & 31;
                dst = g_kb + ((size_t)(t*H_ + h)*K_ + k)*SA_;
            }
            __nv_bfloat162 h0 = __floats2bfloat162_rn(acc[r][0], acc[r][1]);
            __nv_bfloat162 h1 = __floats2bfloat162_rn(acc[r][2], acc[r][3]);
            float2 f0 = __bfloat1622float2(h0), f1 = __bfloat1622float2(h1);
            __nv_bfloat162 l0 = __floats2bfloat162_rn(acc[r][0] - f0.x, acc[r][1] - f0.y);
            __nv_bfloat162 l1 = __floats2bfloat162_rn(acc[r][2] - f1.x, acc[r][3] - f1.y);
            *(__nv_bfloat162*)(dst + d)          = h0;
            *(__nv_bfloat162*)(dst + d + 2)      = h1;
            *(__nv_bfloat162*)(dst + 64 + d)     = l0;
            *(__nv_bfloat162*)(dst + 64 + d + 2) = l1;
        }
    }
}

__global__ void __launch_bounds__(NT_, 1)
attn_kernel(float* __restrict__ out, int wAttn, int wText) {
    extern __shared__ unsigned char smem[];
    unsigned sbase = smem_u32(smem);
    float* sYO   = (float*)(smem + YO_OFF);
    float* sV    = (float*)(smem + V_OFF);
    float* sRinv = (float*)(smem + RINV_OFF);
    float* sPE   = (float*)(smem + PE_OFF);
    float* sPA   = (float*)(smem + PA_OFF);

    int tid = threadIdx.x, lane = tid & 31, wid = tid >> 5;
    int bid = blockIdx.x;
    int u0 = (bid * NU_) / NCTA_;
    int u1 = ((bid + 1) * NU_) / NCTA_;

    for (int idx = tid; idx < T_*K_; idx += NT_) {
        float m = g_maskf[idx];
        sYO[idx] = (m != 0.f) ? 0.f : -1e30f;
    }
    {
        int ts = (u0 & 63), hs = (u0 >> 6) & 7;
        const float4* bs = (const float4*)(g_kb + (size_t)(ts*H_ + hs)*(K_*SA_));
        float4* bd = (float4*)(smem + B_OFF);
        for (int idx = tid; idx < BBUF/16; idx += NT_) bd[idx] = bs[idx];
        const float4* vs = (const float4*)(g_value + (size_t)(ts*H_ + hs)*(K_*D_));
        float4* vd = (float4*)sV;
        for (int idx = tid; idx < (K_*D_)/4; idx += NT_) vd[idx] = vs[idx];
    }
    __syncthreads();

    unsigned ahi[4][4], alo[4][4];
    int curih = -1;
    const ull S2 = pack2(SC2_, SC2_);
    int g = lane >> 2, q2 = lane & 3;
    // per-thread B ldmatrix x4 offset: lanes 0-15 -> hi matrices, 16-31 -> lo (+128B)
    unsigned boff = (unsigned)(((lane & 7)*SA_ + ((lane >> 3) & 1)*8)*2 + (lane >> 4)*128);

    for (int u = u0; u < u1; u++) {
        int ih = u >> 6, t = u & 63;
        int h = ih & 7, i = ih >> 3;
        int p = (u - u0) & 1;

        if (ih != curih) {
            const float4* qs = (const float4*)(g_qb + (size_t)ih*(MR_*SA_));
            float4* qd = (float4*)(smem + A_OFF);
            for (int idx = tid; idx < ABYTES/16; idx += NT_) qd[idx] = qs[idx];
            __syncthreads();
            if (wid < 13) {
                int lrow = lane & 15;
                int lcol = (lane < 16) ? 0 : 8;
                #pragma unroll
                for (int ks = 0; ks < 4; ks++) {
                    unsigned a0 = sbase + A_OFF + (unsigned)(((wid*16 + lrow)*SA_ + ks*16 + lcol)*2);
                    ldm_x4(a0, ahi[ks][0], ahi[ks][1], ahi[ks][2], ahi[ks][3]);
                    ldm_x4(a0 + 128, alo[ks][0], alo[ks][1], alo[ks][2], alo[ks][3]);
                }
            }
            curih = ih;
        }

        if (wid < 13) {
            unsigned sBb = sbase + B_OFF + (unsigned)(p*BBUF) + boff;
            int r0 = wid*16 + g;
            unsigned yoT = sbase + YO_OFF + (unsigned)(t*128);
            float c[4][4] = {};
            #pragma unroll
            for (int ks = 0; ks < 4; ks++) {
                unsigned bh0[4], bh1[4], bl0[4], bl1[4];
                #pragma unroll
                for (int nt = 0; nt < 4; nt++) {
                    unsigned ab = sBb + (unsigned)((nt*8*SA_ + ks*16)*2);
                    ldm_x4(ab, bh0[nt], bh1[nt], bl0[nt], bl1[nt]);
                }
                #pragma unroll
                for (int nt = 0; nt < 4; nt++) {
                    mma_bf16(c[nt], ahi[ks], bh0[nt], bh1[nt]);
                    mma_bf16(c[nt], alo[ks], bh0[nt], bh1[nt]);
                    mma_bf16(c[nt], ahi[ks], bl0[nt], bl1[nt]);
                }
            }
            ull e0[4], e1[4];
            ull rs0 = pack2(0.f, 0.f), rs1 = pack2(0.f, 0.f);
            #pragma unroll
            for (int nt = 0; nt < 4; nt++) {
                ull yo = lds1(yoT + (unsigned)((nt*8 + 2*q2)*4));
                ull v0 = fma2(pack2(c[nt][0], c[nt][1]), S2, yo);
                ull v1 = fma2(pack2(c[nt][2], c[nt][3]), S2, yo);
                e0[nt] = pack2(ex2(lo2(v0)), ex2(hi2(v0)));
                e1[nt] = pack2(ex2(lo2(v1)), ex2(hi2(v1)));
                rs0 = add2(rs0, e0[nt]);
                rs1 = add2(rs1, e1[nt]);
            }
            float* sEp = (float*)(smem + SE_OFF + p*SEBUF);
            #pragma unroll
            for (int nt = 0; nt < 4; nt++) {
                int col = nt*8 + 2*q2;
                *(float2*)&sEp[r0*EST_ + col]       = make_float2(lo2(e0[nt]), hi2(e0[nt]));
                *(float2*)&sEp[(r0 + 8)*EST_ + col] = make_float2(lo2(e1[nt]), hi2(e1[nt]));
            }
            float rsum0 = lo2(rs0) + hi2(rs0);
            float rsum1 = lo2(rs1) + hi2(rs1);
            rsum0 += __shfl_xor_sync(0xffffffffu, rsum0, 1);
            rsum0 += __shfl_xor_sync(0xffffffffu, rsum0, 2);
            rsum1 += __shfl_xor_sync(0xffffffffu, rsum1, 1);
            rsum1 += __shfl_xor_sync(0xffffffffu, rsum1, 2);
            float rinv0 = rcpa(rsum0), rinv1 = rcpa(rsum1);
            if (q2 == 0) { sRinv[p*208 + r0] = rinv0; sRinv[p*208 + r0 + 8] = rinv1; }
            float m0f = (r0 < Q_) ? 1.f : 0.f;
            float m1f = (r0 + 8 < Q_) ? 1.f : 0.f;
            ull M0 = pack2(m0f, m0f), M1 = pack2(m1f, m1f);
            ull rv0p = pack2(rinv0*m0f, rinv0*m0f);
            ull rv1p = pack2(rinv1*m1f, rinv1*m1f);
            #pragma unroll
            for (int nt = 0; nt < 4; nt++) {
                ull pe2 = fma2(e1[nt], M1, mul2(e0[nt], M0));
                ull pa2 = fma2(e1[nt], rv1p, mul2(e0[nt], rv0p));
                float pex = lo2(pe2), pey = hi2(pe2), pax = lo2(pa2), pay = hi2(pa2);
                #pragma unroll
                for (int o = 4; o <= 16; o <<= 1) {
                    pex += __shfl_xor_sync(0xffffffffu, pex, o);
                    pey += __shfl_xor_sync(0xffffffffu, pey, o);
                    pax += __shfl_xor_sync(0xffffffffu, pax, o);
                    pay += __shfl_xor_sync(0xffffffffu, pay, o);
                }
                if (lane < 4) {
                    int col = nt*8 + 2*lane;
                    sPE[p*512 + wid*32 + col] = pex; sPE[p*512 + wid*32 + col + 1] = pey;
                    sPA[p*512 + wid*32 + col] = pax; sPA[p*512 + wid*32 + col + 1] = pay;
                }
            }
        } else if (u + 1 < u1) {
            int un = u + 1, tn = un & 63, hn = (un >> 6) & 7;
            int pn = p ^ 1, vn = (un - u0) % 3;
            int idx0 = tid - 416;
            const unsigned char* bs = (const unsigned char*)(g_kb + (size_t)(tn*H_ + hn)*(K_*SA_));
            unsigned bd = sbase + B_OFF + (unsigned)(pn*BBUF);
            for (int idx = idx0; idx < BBUF/16; idx += 96)
                cpa16(bd + idx*16, bs + idx*16);
            const unsigned char* vs = (const unsigned char*)(g_value + (size_t)(tn*H_ + hn)*(K_*D_));
            unsigned vd = sbase + V_OFF + (unsigned)(vn*VBUF);
            for (int idx = idx0; idx < VBUF/16; idx += 96)
                cpa16(vd + idx*16, vs + idx*16);
            CPA_COMMIT();
        }

        if (u > u0) {
            int pu = u - 1;
            int pt = pu & 63, pih = pu >> 6;
            int ph = pih & 7, pi = pih >> 3;
            int pp = (pu - u0) & 1;
            int pv = (pu - u0) % 3;
            long long pOff = ((long long)(pi*T_ + pt)*H_ + ph) * (Q_*K_);
            float pe = 0.f, pa = 0.f;
            #pragma unroll
            for (int w = 0; w < 13; w++) {
                pe += sPE[pp*512 + w*32 + lane];
                pa += sPA[pp*512 + w*32 + lane];
            }
            float yv = sYO[pt*K_ + lane];
            float ta = (yv == 0.f) ? rcpa(pe) : 0.f;
            float tb = (yv == 0.f) ? 0.f : (1.f / (float)Q_);
            if (wAttn | wText) {
                float* ap = out + OUT_N + pOff;
                float* tp = out + OUT_N + (long long)ATT_N + pOff;
                unsigned seb = sbase + SE_OFF + (unsigned)(pp*SEBUF);
                #pragma unroll
                for (int kk = 0; kk < 4; kk++) {
                    int idx = tid + kk*NT_;
                    if (idx >= Q_*8) break;
                    int q = idx >> 3, c = idx & 7;
                    ull ev0, ev1;
                    lds2(seb + (unsigned)((q*EST_ + 4*c)*4), ev0, ev1);
                    if (wAttn) {
                        float rq = sRinv[pp*208 + q];
                        ull rv = pack2(rq, rq);
                        stg4(ap + q*K_ + 4*c, mul2(ev0, rv), mul2(ev1, rv));
                    }
                    if (wText) {
                        float tax = __shfl_sync(0xffffffffu, ta, 4*c);
                        float tay = __shfl_sync(0xffffffffu, ta, 4*c + 1);
                        float taz = __shfl_sync(0xffffffffu, ta, 4*c + 2);
                        float taw = __shfl_sync(0xffffffffu, ta, 4*c + 3);
                        float tbx = __shfl_sync(0xffffffffu, tb, 4*c);
                        float tby = __shfl_sync(0xffffffffu, tb, 4*c + 1);
                        float tbz = __shfl_sync(0xffffffffu, tb, 4*c + 2);
                        float tbw = __shfl_sync(0xffffffffu, tb, 4*c + 3);
                        stg4(tp + q*K_ + 4*c,
                             fma2(ev0, pack2(tax, tay), pack2(tbx, tby)),
                             fma2(ev1, pack2(taz, taw), pack2(tbz, tbw)));
                    }
                }
            }
            if (wid == 13 || wid == 14) {
                int d = (wid - 13)*32 + lane;
                const float* vv = sV + pv*(K_*D_);
                float a = 0.f;
                #pragma unroll
                for (int k = 0; k < 32; k++)
                    a = fmaf(__shfl_sync(0xffffffffu, pa, k), vv[k*D_ + d], a);
                g_pooled[(long long)(pi*T_ + pt)*E_ + ph*64 + d] = a * (1.f / (float)Q_);
            }
        }
        if (wid >= 13) CPA_WAIT();
        __syncthreads();
    }

    {   // drain last unit
        int pu = u1 - 1;
        int pt = pu & 63, pih = pu >> 6;
        int ph = pih & 7, pi = pih >> 3;
        int pp = (pu - u0) & 1;
        int pv = (pu - u0) % 3;
        long long pOff = ((long long)(pi*T_ + pt)*H_ + ph) * (Q_*K_);
        float pe = 0.f, pa = 0.f;
        #pragma unroll
        for (int w = 0; w < 13; w++) {
            pe += sPE[pp*512 + w*32 + lane];
            pa += sPA[pp*512 + w*32 + lane];
        }
        float yv = sYO[pt*K_ + lane];
        float ta = (yv == 0.f) ? rcpa(pe) : 0.f;
        float tb = (yv == 0.f) ? 0.f : (1.f / (float)Q_);
        if (wAttn | wText) {
            float* ap = out + OUT_N + pOff;
            float* tp = out + OUT_N + (long long)ATT_N + pOff;
            unsigned seb = sbase + SE_OFF + (unsigned)(pp*SEBUF);
            #pragma unroll
            for (int kk = 0; kk < 4; kk++) {
                int idx = tid + kk*NT_;
                if (idx >= Q_*8) break;
                int q = idx >> 3, c = idx & 7;
                ull ev0, ev1;
                lds2(seb + (unsigned)((q*EST_ + 4*c)*4), ev0, ev1);
                if (wAttn) {
                    float rq = sRinv[pp*208 + q];
                    ull rv = pack2(rq, rq);
                    stg4(ap + q*K_ + 4*c, mul2(ev0, rv), mul2(ev1, rv));
                }
                if (wText) {
                    float tax = __shfl_sync(0xffffffffu, ta, 4*c);
                    float tay = __shfl_sync(0xffffffffu, ta, 4*c + 1);
                    float taz = __shfl_sync(0xffffffffu, ta, 4*c + 2);
                    float taw = __shfl_sync(0xffffffffu, ta, 4*c + 3);
                    float tbx = __shfl_sync(0xffffffffu, tb, 4*c);
                    float tby = __shfl_sync(0xffffffffu, tb, 4*c + 1);
                    float tbz = __shfl_sync(0xffffffffu, tb, 4*c + 2);
                    float tbw = __shfl_sync(0xffffffffu, tb, 4*c + 3);
                    stg4(tp + q*K_ + 4*c,
                         fma2(ev0, pack2(tax, tay), pack2(tbx, tby)),
                         fma2(ev1, pack2(taz, taw), pack2(tbz, tbw)));
                }
            }
        }
        if (wid == 13 || wid == 14) {
            int d = (wid - 13)*32 + lane;
            const float* vv = sV + pv*(K_*D_);
            float a = 0.f;
            #pragma unroll
            for (int k = 0; k < 32; k++)
                a = fmaf(__shfl_sync(0xffffffffu, pa, k), vv[k*D_ + d], a);
            g_pooled[(long long)(pi*T_ + pt)*E_ + ph*64 + d] = a * (1.f / (float)Q_);
        }
    }
}

__global__ void __launch_bounds__(256, 2)
fc_kernel(const float* __restrict__ Wo, const float* __restrict__ bo,
          float* __restrict__ out) {
    __shared__ float sA[32*33];
    __shared__ float sB[64*33];
    int rt = blockIdx.x * 32;
    int ct = blockIdx.y * 64;
    int tid = threadIdx.x;
    int tx = tid & 15, ty = tid >> 4;
    float acc[2][4] = {};
    float ra[4], rb[8];
    #pragma unroll
    for (int j = 0; j < 4; j++) {
        int idx = tid + j*256;
        ra[j] = g_pooled[(rt + (idx >> 5))*E_ + (idx & 31)];
    }
    #pragma unroll
    for (int j = 0; j < 8; j++) {
        int idx = tid + j*256;
        rb[j] = Wo[(ct + (idx >> 5))*E_ + (idx & 31)];
    }
    for (int kc = 0; kc < E_; kc += 32) {
        #pragma unroll
        for (int j = 0; j < 4; j++) {
            int idx = tid + j*256;
            sA[(idx >> 5)*33 + (idx & 31)] = ra[j];
        }
        #pragma unroll
        for (int j = 0; j < 8; j++) {
            int idx = tid + j*256;
            sB[(idx >> 5)*33 + (idx & 31)] = rb[j];
        }
        __syncthreads();
        if (kc + 32 < E_) {
            #pragma unroll
            for (int j = 0; j < 4; j++) {
                int idx = tid + j*256;
                ra[j] = g_pooled[(rt + (idx >> 5))*E_ + kc + 32 + (idx & 31)];
            }
            #pragma unroll
            for (int j = 0; j < 8; j++) {
                int idx = tid + j*256;
                rb[j] = Wo[(ct + (idx >> 5))*E_ + kc + 32 + (idx & 31)];
            }
        }
        #pragma unroll
        for (int kk = 0; kk < 32; kk++) {
            float a[2], b[4];
            #pragma unroll
            for (int r = 0; r < 2; r++) a[r] = sA[(ty*2 + r)*33 + kk];
            #pragma unroll
            for (int c = 0; c < 4; c++) b[c] = sB[(tx*4 + c)*33 + kk];
            #pragma unroll
            for (int r = 0; r < 2; r++)
                #pragma unroll
                for (int c = 0; c < 4; c++) acc[r][c] += a[r] * b[c];
        }
        __syncthreads();
    }
    #pragma unroll
    for (int r = 0; r < 2; r++)
        #pragma unroll
        for (int c = 0; c < 4; c++)
            out[(rt + ty*2 + r)*E_ + ct + tx*4 + c] = acc[r][c] + bo[ct + tx*4 + c];
}

extern "C" void kernel_launch(void* const* d_in, const int* in_sizes, int n_in,
                              void* d_out, int out_size) {
    const float* image = (const float*)d_in[0];
    const float* text  = (const float*)d_in[1];
    const void*  mask  =                d_in[2];
    const float* Wq    = (const float*)d_in[3];
    const float* Wk    = (const float*)d_in[4];
    const float* Wv    = (const float*)d_in[5];
    const float* Wo    = (const float*)d_in[6];
    const float* bo    = (const float*)d_in[7];
    float* out = (float*)d_out;

    cudaFuncSetAttribute(attn_kernel, cudaFuncAttributeMaxDynamicSharedMemorySize, SMEM_ATTN);

    prep_all<<<905, 256>>>(image, text, Wq, Wk, Wv, mask);

    int wAttn = out_size >= (OUT_N + ATT_N);
    int wText = out_size >= (OUT_N + 2*ATT_N);
    attn_kernel<<<NCTA_, NT_, SMEM_ATTN>>>(out, wAttn, wText);

    if (out_size >= OUT_N)
        fc_kernel<<<dim3(32, 8), 256>>>(Wo, bo, out);
}

// round 17
// speedup vs baseline: 1.0826x; 1.0037x over previous
#include <cuda_runtime.h>
#include <cuda_bf16.h>
#include <math.h>
#include <cstdint>

#define I_ 16
#define T_ 64
#define Q_ 196
#define K_ 32
#define E_ 512
#define H_ 8
#define D_ 64
#define NT_ 512
#define NCTA_ 148
#define NU_ (I_*H_*T_)

#define OUT_N   (I_*T_*E_)
#define ATT_N   (I_*T_*H_*Q_*K_)
#define SC2_    ((float)(0.044194173824159216*1.4426950408889634))

#define SA_  136
#define MR_  208
#define EST_ 36
#define BBUF (K_*SA_*2)                 // 8704
#define VBUF (K_*D_*4)                  // 8192
#define ABYTES (MR_*SA_*2)              // 56576
#define SEBUF (MR_*EST_*4)              // 29952

#define A_OFF    0
#define SE_OFF   56576
#define YO_OFF   116480
#define B_OFF    124672
#define V_OFF    142080
#define RINV_OFF 166656
#define PE_OFF   168320
#define PA_OFF   172416
#define SMEM_ATTN 176512

typedef unsigned long long ull;

__device__ float g_value[T_*H_*K_*D_];
__device__ float g_pooled[I_*T_*E_];
__device__ float g_maskf[T_*K_];
__device__ __nv_bfloat16 g_qb[(size_t)I_*H_*MR_*SA_];   // pre-split A tiles, zero-padded
__device__ __nv_bfloat16 g_kb[(size_t)T_*H_*K_*SA_];    // pre-split B tiles

__device__ __forceinline__ unsigned smem_u32(const void* p) {
    unsigned a;
    asm("{ .reg .u64 t; cvta.to.shared.u64 t, %1; cvt.u32.u64 %0, t; }" : "=r"(a) : "l"(p));
    return a;
}
__device__ __forceinline__ ull fma2(ull a, ull b, ull c) {
    ull d; asm("fma.rn.f32x2 %0, %1, %2, %3;" : "=l"(d) : "l"(a), "l"(b), "l"(c)); return d;
}
__device__ __forceinline__ ull mul2(ull a, ull b) {
    ull d; asm("mul.rn.f32x2 %0, %1, %2;" : "=l"(d) : "l"(a), "l"(b)); return d;
}
__device__ __forceinline__ ull add2(ull a, ull b) {
    ull d; asm("add.rn.f32x2 %0, %1, %2;" : "=l"(d) : "l"(a), "l"(b)); return d;
}
__device__ __forceinline__ ull pack2(float x, float y) {
    ull d; asm("mov.b64 %0, {%1, %2};" : "=l"(d) : "f"(x), "f"(y)); return d;
}
__device__ __forceinline__ float lo2(ull a) { return __uint_as_float((unsigned)a); }
__device__ __forceinline__ float hi2(ull a) { return __uint_as_float((unsigned)(a >> 32)); }
__device__ __forceinline__ float ex2(float x) {
    float y; asm("ex2.approx.f32 %0, %1;" : "=f"(y) : "f"(x)); return y;
}
__device__ __forceinline__ float rcpa(float x) {
    float y; asm("rcp.approx.f32 %0, %1;" : "=f"(y) : "f"(x)); return y;
}
__device__ __forceinline__ ull lds1(unsigned a) {
    ull x; asm volatile("ld.shared.b64 %0, [%1];" : "=l"(x) : "r"(a)); return x;
}
__device__ __forceinline__ void lds2(unsigned a, ull& x, ull& y) {
    asm volatile("ld.shared.v2.b64 {%0,%1}, [%2];" : "=l"(x), "=l"(y) : "r"(a));
}
__device__ __forceinline__ void stg4(float* p, ull a, ull b) {
    asm volatile("{ .reg .f32 x,y,z,w; mov.b64 {x,y}, %1; mov.b64 {z,w}, %2;"
                 " st.global.v4.f32 [%0], {x,y,z,w}; }" :: "l"(p), "l"(a), "l"(b) : "memory");
}
__device__ __forceinline__ void cpa16(unsigned dst, const void* src) {
    asm volatile("cp.async.cg.shared.global [%0], [%1], 16;" :: "r"(dst), "l"(src) : "memory");
}
#define CPA_COMMIT() asm volatile("cp.async.commit_group;" ::: "memory")
#define CPA_WAIT()   asm volatile("cp.async.wait_group 0;" ::: "memory")
__device__ __forceinline__ void ldm_x4(unsigned a, unsigned& r0, unsigned& r1,
                                       unsigned& r2, unsigned& r3) {
    asm volatile("ldmatrix.sync.aligned.m8n8.x4.shared.b16 {%0,%1,%2,%3}, [%4];"
                 : "=r"(r0), "=r"(r1), "=r"(r2), "=r"(r3) : "r"(a));
}
__device__ __forceinline__ void mma_bf16(float* c, const unsigned* a, unsigned b0, unsigned b1) {
    asm volatile("mma.sync.aligned.m16n8k16.row.col.f32.bf16.bf16.f32 "
                 "{%0,%1,%2,%3}, {%4,%5,%6,%7}, {%8,%9}, {%0,%1,%2,%3};"
                 : "+f"(c[0]), "+f"(c[1]), "+f"(c[2]), "+f"(c[3])
                 : "r"(a[0]), "r"(a[1]), "r"(a[2]), "r"(a[3]), "r"(b0), "r"(b1));
}

// ---- prep v2: 128x64 tiles, 8x4 microtile, reg double-buffered staging ----
// grid 457: [0,200) Q (h*25+rb), [200,328) K, [328,456) V, 456 = mask
__global__ void __launch_bounds__(256, 3)
prep_all(const float* __restrict__ image, const float* __restrict__ text,
         const float* __restrict__ Wq, const float* __restrict__ Wk,
         const float* __restrict__ Wv, const void* mp) {
    int bid = blockIdx.x;
    int tid = threadIdx.x;
    if (bid == 456) {
        __shared__ int mode;
        if (tid == 0) {
            const unsigned char* b = (const unsigned char*)mp;
            int c3f = 0, cnz = 0;
            for (int k = 0; k < 512; k++) {
                if (b[4*k+3] == 0x3F) c3f++;
                if (b[4*k+1] | b[4*k+2]) cnz++;
            }
            mode = (c3f > 8) ? 2 : ((cnz > 8) ? 0 : 1);
        }
        __syncthreads();
        int m = mode;
        for (int idx = tid; idx < T_*K_; idx += blockDim.x) {
            float v;
            if (m == 0)      v = ((const unsigned char*)mp)[idx] ? 1.f : 0.f;
            else if (m == 1) v = ((const int*)mp)[idx] ? 1.f : 0.f;
            else             v = (((const float*)mp)[idx] != 0.f) ? 1.f : 0.f;
            g_maskf[idx] = v;
        }
        return;
    }

    __shared__ float sX[128*33];
    __shared__ float sW[64*33];
    int which, h, rb;
    const float *X, *W;
    if (bid < 200)      { which = 0; h = bid/25;       rb = bid%25;       X = image; W = Wq; }
    else if (bid < 328) { which = 1; h = (bid-200)/16; rb = (bid-200)%16; X = text;  W = Wk; }
    else                { which = 2; h = (bid-328)/16; rb = (bid-328)%16; X = text;  W = Wv; }
    int r0 = bid < 200 ? rb*128 : rb*128;
    int nrows = (which == 0) ? ((I_*Q_) - r0 < 128 ? (I_*Q_) - r0 : 128) : 128;

    int tx = tid & 15, ty = tid >> 4;
    float acc[8][4] = {};
    float rx[16], rw[8];

    // prefetch chunk 0
    #pragma unroll
    for (int j = 0; j < 16; j++) {
        int idx = tid + j*256;
        int r = idx >> 5, kk = idx & 31;
        rx[j] = (r < nrows) ? X[(r0 + r)*E_ + h*64 + kk] : 0.f;
    }
    #pragma unroll
    for (int j = 0; j < 8; j++) {
        int idx = tid + j*256;
        rw[j] = W[(idx >> 5)*64 + (idx & 31)];
    }

    #pragma unroll
    for (int kc = 0; kc < 64; kc += 32) {
        #pragma unroll
        for (int j = 0; j < 16; j++) {
            int idx = tid + j*256;
            sX[(idx >> 5)*33 + (idx & 31)] = rx[j];
        }
        #pragma unroll
        for (int j = 0; j < 8; j++) {
            int idx = tid + j*256;
            sW[(idx >> 5)*33 + (idx & 31)] = rw[j];
        }
        __syncthreads();
        if (kc == 0) {
            #pragma unroll
            for (int j = 0; j < 16; j++) {
                int idx = tid + j*256;
                int r = idx >> 5, kk = idx & 31;
                rx[j] = (r < nrows) ? X[(r0 + r)*E_ + h*64 + 32 + kk] : 0.f;
            }
            #pragma unroll
            for (int j = 0; j < 8; j++) {
                int idx = tid + j*256;
                rw[j] = W[(idx >> 5)*64 + 32 + (idx & 31)];
            }
        }
        #pragma unroll
        for (int kk = 0; kk < 32; kk++) {
            float a[8], b[4];
            #pragma unroll
            for (int r = 0; r < 8; r++) a[r] = sX[(ty*8 + r)*33 + kk];
            #pragma unroll
            for (int c = 0; c < 4; c++) b[c] = sW[(tx*4 + c)*33 + kk];
            #pragma unroll
            for (int r = 0; r < 8; r++)
                #pragma unroll
                for (int c = 0; c < 4; c++) acc[r][c] += a[r] * b[c];
        }
        __syncthreads();
    }

    int d = tx*4;
    #pragma unroll
    for (int r = 0; r < 8; r++) {
        int lr = ty*8 + r;
        if (lr >= nrows) break;
        int row = r0 + lr;
        if (which == 2) {
            int t = row >> 5, k = row & 31;
            long long ob = ((long long)(t*H_ + h)*K_ + k)*64 + d;
            #pragma unroll
            for (int c = 0; c < 4; c++) g_value[ob + c] = acc[r][c];
        } else {
            __nv_bfloat16* dst;
            if (which == 0) {
                int i = row / Q_, q = row % Q_;
                dst = g_qb + ((size_t)(i*H_ + h)*MR_ + q)*SA_;
            } else {
                int t = row >> 5, k = row & 31;
                dst = g_kb + ((size_t)(t*H_ + h)*K_ + k)*SA_;
            }
            __nv_bfloat162 h0 = __floats2bfloat162_rn(acc[r][0], acc[r][1]);
            __nv_bfloat162 h1 = __floats2bfloat162_rn(acc[r][2], acc[r][3]);
            float2 f0 = __bfloat1622float2(h0), f1 = __bfloat1622float2(h1);
            __nv_bfloat162 l0 = __floats2bfloat162_rn(acc[r][0] - f0.x, acc[r][1] - f0.y);
            __nv_bfloat162 l1 = __floats2bfloat162_rn(acc[r][2] - f1.x, acc[r][3] - f1.y);
            *(__nv_bfloat162*)(dst + d)          = h0;
            *(__nv_bfloat162*)(dst + d + 2)      = h1;
            *(__nv_bfloat162*)(dst + 64 + d)     = l0;
            *(__nv_bfloat162*)(dst + 64 + d + 2) = l1;
        }
    }
}

__global__ void __launch_bounds__(NT_, 1)
attn_kernel(float* __restrict__ out, int wAttn, int wText) {
    extern __shared__ unsigned char smem[];
    unsigned sbase = smem_u32(smem);
    float* sYO   = (float*)(smem + YO_OFF);
    float* sV    = (float*)(smem + V_OFF);
    float* sRinv = (float*)(smem + RINV_OFF);
    float* sPE   = (float*)(smem + PE_OFF);
    float* sPA   = (float*)(smem + PA_OFF);

    int tid = threadIdx.x, lane = tid & 31, wid = tid >> 5;
    int bid = blockIdx.x;
    int u0 = (bid * NU_) / NCTA_;
    int u1 = ((bid + 1) * NU_) / NCTA_;

    for (int idx = tid; idx < T_*K_; idx += NT_) {
        float m = g_maskf[idx];
        sYO[idx] = (m != 0.f) ? 0.f : -1e30f;
    }
    {
        int ts = (u0 & 63), hs = (u0 >> 6) & 7;
        const float4* bs = (const float4*)(g_kb + (size_t)(ts*H_ + hs)*(K_*SA_));
        float4* bd = (float4*)(smem + B_OFF);
        for (int idx = tid; idx < BBUF/16; idx += NT_) bd[idx] = bs[idx];
        const float4* vs = (const float4*)(g_value + (size_t)(ts*H_ + hs)*(K_*D_));
        float4* vd = (float4*)sV;
        for (int idx = tid; idx < (K_*D_)/4; idx += NT_) vd[idx] = vs[idx];
    }
    __syncthreads();

    unsigned ahi[4][4], alo[4][4];
    int curih = -1;
    const ull S2 = pack2(SC2_, SC2_);
    int g = lane >> 2, q2 = lane & 3;
    unsigned boff = (unsigned)(((lane & 7)*SA_ + ((lane >> 3) & 1)*8)*2 + (lane >> 4)*128);

    for (int u = u0; u < u1; u++) {
        int ih = u >> 6, t = u & 63;
        int h = ih & 7, i = ih >> 3;
        int p = (u - u0) & 1;

        if (ih != curih) {
            const float4* qs = (const float4*)(g_qb + (size_t)ih*(MR_*SA_));
            float4* qd = (float4*)(smem + A_OFF);
            for (int idx = tid; idx < ABYTES/16; idx += NT_) qd[idx] = qs[idx];
            __syncthreads();
            if (wid < 13) {
                int lrow = lane & 15;
                int lcol = (lane < 16) ? 0 : 8;
                #pragma unroll
                for (int ks = 0; ks < 4; ks++) {
                    unsigned a0 = sbase + A_OFF + (unsigned)(((wid*16 + lrow)*SA_ + ks*16 + lcol)*2);
                    ldm_x4(a0, ahi[ks][0], ahi[ks][1], ahi[ks][2], ahi[ks][3]);
                    ldm_x4(a0 + 128, alo[ks][0], alo[ks][1], alo[ks][2], alo[ks][3]);
                }
            }
            curih = ih;
        }

        if (wid < 13) {
            unsigned sBb = sbase + B_OFF + (unsigned)(p*BBUF) + boff;
            int r0 = wid*16 + g;
            unsigned yoT = sbase + YO_OFF + (unsigned)(t*128);
            float c[4][4] = {};
            #pragma unroll
            for (int ks = 0; ks < 4; ks++) {
                unsigned bh0[4], bh1[4], bl0[4], bl1[4];
                #pragma unroll
                for (int nt = 0; nt < 4; nt++) {
                    unsigned ab = sBb + (unsigned)((nt*8*SA_ + ks*16)*2);
                    ldm_x4(ab, bh0[nt], bh1[nt], bl0[nt], bl1[nt]);
                }
                #pragma unroll
                for (int nt = 0; nt < 4; nt++) {
                    mma_bf16(c[nt], ahi[ks], bh0[nt], bh1[nt]);
                    mma_bf16(c[nt], alo[ks], bh0[nt], bh1[nt]);
                    mma_bf16(c[nt], ahi[ks], bl0[nt], bl1[nt]);
                }
            }
            ull e0[4], e1[4];
            ull rs0 = pack2(0.f, 0.f), rs1 = pack2(0.f, 0.f);
            #pragma unroll
            for (int nt = 0; nt < 4; nt++) {
                ull yo = lds1(yoT + (unsigned)((nt*8 + 2*q2)*4));
                ull v0 = fma2(pack2(c[nt][0], c[nt][1]), S2, yo);
                ull v1 = fma2(pack2(c[nt][2], c[nt][3]), S2, yo);
                e0[nt] = pack2(ex2(lo2(v0)), ex2(hi2(v0)));
                e1[nt] = pack2(ex2(lo2(v1)), ex2(hi2(v1)));
                rs0 = add2(rs0, e0[nt]);
                rs1 = add2(rs1, e1[nt]);
            }
            float* sEp = (float*)(smem + SE_OFF + p*SEBUF);
            #pragma unroll
            for (int nt = 0; nt < 4; nt++) {
                int col = nt*8 + 2*q2;
                *(float2*)&sEp[r0*EST_ + col]       = make_float2(lo2(e0[nt]), hi2(e0[nt]));
                *(float2*)&sEp[(r0 + 8)*EST_ + col] = make_float2(lo2(e1[nt]), hi2(e1[nt]));
            }
            float rsum0 = lo2(rs0) + hi2(rs0);
            float rsum1 = lo2(rs1) + hi2(rs1);
            rsum0 += __shfl_xor_sync(0xffffffffu, rsum0, 1);
            rsum0 += __shfl_xor_sync(0xffffffffu, rsum0, 2);
            rsum1 += __shfl_xor_sync(0xffffffffu, rsum1, 1);
            rsum1 += __shfl_xor_sync(0xffffffffu, rsum1, 2);
            float rinv0 = rcpa(rsum0), rinv1 = rcpa(rsum1);
            if (q2 == 0) { sRinv[p*208 + r0] = rinv0; sRinv[p*208 + r0 + 8] = rinv1; }
            float m0f = (r0 < Q_) ? 1.f : 0.f;
            float m1f = (r0 + 8 < Q_) ? 1.f : 0.f;
            ull M0 = pack2(m0f, m0f), M1 = pack2(m1f, m1f);
            ull rv0p = pack2(rinv0*m0f, rinv0*m0f);
            ull rv1p = pack2(rinv1*m1f, rinv1*m1f);
            #pragma unroll
            for (int nt = 0; nt < 4; nt++) {
                ull pe2 = fma2(e1[nt], M1, mul2(e0[nt], M0));
                ull pa2 = fma2(e1[nt], rv1p, mul2(e0[nt], rv0p));
                float pex = lo2(pe2), pey = hi2(pe2), pax = lo2(pa2), pay = hi2(pa2);
                #pragma unroll
                for (int o = 4; o <= 16; o <<= 1) {
                    pex += __shfl_xor_sync(0xffffffffu, pex, o);
                    pey += __shfl_xor_sync(0xffffffffu, pey, o);
                    pax += __shfl_xor_sync(0xffffffffu, pax, o);
                    pay += __shfl_xor_sync(0xffffffffu, pay, o);
                }
                if (lane < 4) {
                    int col = nt*8 + 2*lane;
                    sPE[p*512 + wid*32 + col] = pex; sPE[p*512 + wid*32 + col + 1] = pey;
                    sPA[p*512 + wid*32 + col] = pax; sPA[p*512 + wid*32 + col + 1] = pay;
                }
            }
        } else if (u + 1 < u1) {
            int un = u + 1, tn = un & 63, hn = (un >> 6) & 7;
            int pn = p ^ 1, vn = (un - u0) % 3;
            int idx0 = tid - 416;
            const unsigned char* bs = (const unsigned char*)(g_kb + (size_t)(tn*H_ + hn)*(K_*SA_));
            unsigned bd = sbase + B_OFF + (unsigned)(pn*BBUF);
            for (int idx = idx0; idx < BBUF/16; idx += 96)
                cpa16(bd + idx*16, bs + idx*16);
            const unsigned char* vs = (const unsigned char*)(g_value + (size_t)(tn*H_ + hn)*(K_*D_));
            unsigned vd = sbase + V_OFF + (unsigned)(vn*VBUF);
            for (int idx = idx0; idx < VBUF/16; idx += 96)
                cpa16(vd + idx*16, vs + idx*16);
            CPA_COMMIT();
        }

        if (u > u0) {
            int pu = u - 1;
            int pt = pu & 63, pih = pu >> 6;
            int ph = pih & 7, pi = pih >> 3;
            int pp = (pu - u0) & 1;
            int pv = (pu - u0) % 3;
            long long pOff = ((long long)(pi*T_ + pt)*H_ + ph) * (Q_*K_);
            float pe = 0.f, pa = 0.f;
            #pragma unroll
            for (int w = 0; w < 13; w++) {
                pe += sPE[pp*512 + w*32 + lane];
                pa += sPA[pp*512 + w*32 + lane];
            }
            float yv = sYO[pt*K_ + lane];
            float ta = (yv == 0.f) ? rcpa(pe) : 0.f;
            float tb = (yv == 0.f) ? 0.f : (1.f / (float)Q_);
            if (wAttn | wText) {
                float* ap = out + OUT_N + pOff;
                float* tp = out + OUT_N + (long long)ATT_N + pOff;
                unsigned seb = sbase + SE_OFF + (unsigned)(pp*SEBUF);
                #pragma unroll
                for (int kk = 0; kk < 4; kk++) {
                    int idx = tid + kk*NT_;
                    if (idx >= Q_*8) break;
                    int q = idx >> 3, c = idx & 7;
                    ull ev0, ev1;
                    lds2(seb + (unsigned)((q*EST_ + 4*c)*4), ev0, ev1);
                    if (wAttn) {
                        float rq = sRinv[pp*208 + q];
                        ull rv = pack2(rq, rq);
                        stg4(ap + q*K_ + 4*c, mul2(ev0, rv), mul2(ev1, rv));
                    }
                    if (wText) {
                        float tax = __shfl_sync(0xffffffffu, ta, 4*c);
                        float tay = __shfl_sync(0xffffffffu, ta, 4*c + 1);
                        float taz = __shfl_sync(0xffffffffu, ta, 4*c + 2);
                        float taw = __shfl_sync(0xffffffffu, ta, 4*c + 3);
                        float tbx = __shfl_sync(0xffffffffu, tb, 4*c);
                        float tby = __shfl_sync(0xffffffffu, tb, 4*c + 1);
                        float tbz = __shfl_sync(0xffffffffu, tb, 4*c + 2);
                        float tbw = __shfl_sync(0xffffffffu, tb, 4*c + 3);
                        stg4(tp + q*K_ + 4*c,
                             fma2(ev0, pack2(tax, tay), pack2(tbx, tby)),
                             fma2(ev1, pack2(taz, taw), pack2(tbz, tbw)));
                    }
                }
            }
            if (wid == 13 || wid == 14) {
                int d = (wid - 13)*32 + lane;
                const float* vv = sV + pv*(K_*D_);
                float a = 0.f;
                #pragma unroll
                for (int k = 0; k < 32; k++)
                    a = fmaf(__shfl_sync(0xffffffffu, pa, k), vv[k*D_ + d], a);
                g_pooled[(long long)(pi*T_ + pt)*E_ + ph*64 + d] = a * (1.f / (float)Q_);
            }
        }
        if (wid >= 13) CPA_WAIT();
        __syncthreads();
    }

    {   // drain last unit
        int pu = u1 - 1;
        int pt = pu & 63, pih = pu >> 6;
        int ph = pih & 7, pi = pih >> 3;
        int pp = (pu - u0) & 1;
        int pv = (pu - u0) % 3;
        long long pOff = ((long long)(pi*T_ + pt)*H_ + ph) * (Q_*K_);
        float pe = 0.f, pa = 0.f;
        #pragma unroll
        for (int w = 0; w < 13; w++) {
            pe += sPE[pp*512 + w*32 + lane];
            pa += sPA[pp*512 + w*32 + lane];
        }
        float yv = sYO[pt*K_ + lane];
        float ta = (yv == 0.f) ? rcpa(pe) : 0.f;
        float tb = (yv == 0.f) ? 0.f : (1.f / (float)Q_);
        if (wAttn | wText) {
            float* ap = out + OUT_N + pOff;
            float* tp = out + OUT_N + (long long)ATT_N + pOff;
            unsigned seb = sbase + SE_OFF + (unsigned)(pp*SEBUF);
            #pragma unroll
            for (int kk = 0; kk < 4; kk++) {
                int idx = tid + kk*NT_;
                if (idx >= Q_*8) break;
                int q = idx >> 3, c = idx & 7;
                ull ev0, ev1;
                lds2(seb + (unsigned)((q*EST_ + 4*c)*4), ev0, ev1);
                if (wAttn) {
                    float rq = sRinv[pp*208 + q];
                    ull rv = pack2(rq, rq);
                    stg4(ap + q*K_ + 4*c, mul2(ev0, rv), mul2(ev1, rv));
                }
                if (wText) {
                    float tax = __shfl_sync(0xffffffffu, ta, 4*c);
                    float tay = __shfl_sync(0xffffffffu, ta, 4*c + 1);
                    float taz = __shfl_sync(0xffffffffu, ta, 4*c + 2);
                    float taw = __shfl_sync(0xffffffffu, ta, 4*c + 3);
                    float tbx = __shfl_sync(0xffffffffu, tb, 4*c);
                    float tby = __shfl_sync(0xffffffffu, tb, 4*c + 1);
                    float tbz = __shfl_sync(0xffffffffu, tb, 4*c + 2);
                    float tbw = __shfl_sync(0xffffffffu, tb, 4*c + 3);
                    stg4(tp + q*K_ + 4*c,
                         fma2(ev0, pack2(tax, tay), pack2(tbx, tby)),
                         fma2(ev1, pack2(taz, taw), pack2(tbz, tbw)));
                }
            }
        }
        if (wid == 13 || wid == 14) {
            int d = (wid - 13)*32 + lane;
            const float* vv = sV + pv*(K_*D_);
            float a = 0.f;
            #pragma unroll
            for (int k = 0; k < 32; k++)
                a = fmaf(__shfl_sync(0xffffffffu, pa, k), vv[k*D_ + d], a);
            g_pooled[(long long)(pi*T_ + pt)*E_ + ph*64 + d] = a * (1.f / (float)Q_);
        }
    }
}

__global__ void __launch_bounds__(256, 2)
fc_kernel(const float* __restrict__ Wo, const float* __restrict__ bo,
          float* __restrict__ out) {
    __shared__ float sA[32*33];
    __shared__ float sB[64*33];
    int rt = blockIdx.x * 32;
    int ct = blockIdx.y * 64;
    int tid = threadIdx.x;
    int tx = tid & 15, ty = tid >> 4;
    float acc[2][4] = {};
    float ra[4], rb[8];
    #pragma unroll
    for (int j = 0; j < 4; j++) {
        int idx = tid + j*256;
        ra[j] = g_pooled[(rt + (idx >> 5))*E_ + (idx & 31)];
    }
    #pragma unroll
    for (int j = 0; j < 8; j++) {
        int idx = tid + j*256;
        rb[j] = Wo[(ct + (idx >> 5))*E_ + (idx & 31)];
    }
    for (int kc = 0; kc < E_; kc += 32) {
        #pragma unroll
        for (int j = 0; j < 4; j++) {
            int idx = tid + j*256;
            sA[(idx >> 5)*33 + (idx & 31)] = ra[j];
        }
        #pragma unroll
        for (int j = 0; j < 8; j++) {
            int idx = tid + j*256;
            sB[(idx >> 5)*33 + (idx & 31)] = rb[j];
        }
        __syncthreads();
        if (kc + 32 < E_) {
            #pragma unroll
            for (int j = 0; j < 4; j++) {
                int idx = tid + j*256;
                ra[j] = g_pooled[(rt + (idx >> 5))*E_ + kc + 32 + (idx & 31)];
            }
            #pragma unroll
            for (int j = 0; j < 8; j++) {
                int idx = tid + j*256;
                rb[j] = Wo[(ct + (idx >> 5))*E_ + kc + 32 + (idx & 31)];
            }
        }
        #pragma unroll
        for (int kk = 0; kk < 32; kk++) {
            float a[2], b[4];
            #pragma unroll
            for (int r = 0; r < 2; r++) a[r] = sA[(ty*2 + r)*33 + kk];
            #pragma unroll
            for (int c = 0; c < 4; c++) b[c] = sB[(tx*4 + c)*33 + kk];
            #pragma unroll
            for (int r = 0; r < 2; r++)
                #pragma unroll
                for (int c = 0; c < 4; c++) acc[r][c] += a[r] * b[c];
        }
        __syncthreads();
    }
    #pragma unroll
    for (int r = 0; r < 2; r++)
        #pragma unroll
        for (int c = 0; c < 4; c++)
            out[(rt + ty*2 + r)*E_ + ct + tx*4 + c] = acc[r][c] + bo[ct + tx*4 + c];
}

extern "C" void kernel_launch(void* const* d_in, const int* in_sizes, int n_in,
                              void* d_out, int out_size) {
    const float* image = (const float*)d_in[0];
    const float* text  = (const float*)d_in[1];
    const void*  mask  =                d_in[2];
    const float* Wq    = (const float*)d_in[3];
    const float* Wk    = (const float*)d_in[4];
    const float* Wv    = (const float*)d_in[5];
    const float* Wo    = (const float*)d_in[6];
    const float* bo    = (const float*)d_in[7];
    float* out = (float*)d_out;

    cudaFuncSetAttribute(attn_kernel, cudaFuncAttributeMaxDynamicSharedMemorySize, SMEM_ATTN);

    prep_all<<<457, 256>>>(image, text, Wq, Wk, Wv, mask);

    int wAttn = out_size >= (OUT_N + ATT_N);
    int wText = out_size >= (OUT_N + 2*ATT_N);
    attn_kernel<<<NCTA_, NT_, SMEM_ATTN>>>(out, wAttn, wText);

    if (out_size >= OUT_N)
        fc_kernel<<<dim3(32, 8), 256>>>(Wo, bo, out);
}